// round 1
// baseline (speedup 1.0000x reference)
#include <cuda_runtime.h>

// Problem constants (fixed by the dataset: N=2048, B=2)
#define NN   2048
#define BB   2
#define EW   (NN + 1)            // 2049  E is EW x EW
#define HXH  (NN - 1)            // 2047 rows
#define HXW  (NN)                // 2048 cols
#define HYH  (NN)                // 2048 rows
#define HYW  (NN - 1)            // 2047 cols
#define EN   (EW * EW)           // per-batch E elements
#define HXN  (HXH * HXW)
#define HYN  (HYH * HYW)
#define CFLF 0.35f

// KF = [-11/6, 3, -3/2, 1/3], KB = -reverse(KF)
#define KF0 (-11.0f / 6.0f)
#define KF1 (3.0f)
#define KF2 (-1.5f)
#define KF3 (1.0f / 3.0f)
#define KB0 (-1.0f / 3.0f)
#define KB1 (1.5f)
#define KB2 (-3.0f)
#define KB3 (11.0f / 6.0f)

struct MCoef {
    float M00, M01, M02, M03, M11, M20, M21, M22, M23;
};

__device__ __forceinline__ MCoef make_M(const float* sb, const float* sd, const float* sg) {
    float beta = *sb, delta = *sd, gamma = *sg;
    MCoef m;
    m.M00 = -0.25f * beta + 0.1f * gamma;
    m.M01 =  0.25f * beta + delta - 0.5f - 0.1f * gamma;
    m.M02 =  0.25f * beta - 0.1f * gamma;
    m.M03 = -0.25f * beta + 0.1f * gamma;
    m.M11 = -2.0f * delta;
    m.M20 =  0.25f * beta - 0.1f * gamma;
    m.M21 = -0.25f * beta + delta + 0.5f + 0.1f * gamma;
    m.M22 = -0.25f * beta - 0.1f * gamma;
    m.M23 =  0.25f * beta + 0.1f * gamma;
    return m;
}

// ---------------------------------------------------------------------------
// Amper: E_out[i,j] = E[i,j] + CFL*(s1 - s2),  i,j in [0, NN]
// ---------------------------------------------------------------------------
__global__ void k_amper(const float* __restrict__ E,
                        const float* __restrict__ Hx,
                        const float* __restrict__ Hy,
                        const float* __restrict__ sb,
                        const float* __restrict__ sd,
                        const float* __restrict__ sg,
                        float* __restrict__ Eo)
{
    int j = blockIdx.x * blockDim.x + threadIdx.x;
    int i = blockIdx.y * blockDim.y + threadIdx.y;
    if (i >= EW || j >= EW) return;
    int b = blockIdx.z;

    const float* Eb  = E  + b * EN;
    const float* Hxb = Hx + b * HXN;
    const float* Hyb = Hy + b * HYN;

    MCoef m = make_M(sb, sd, sg);

    float s1 = 0.0f, s2 = 0.0f;
    bool irow = (i >= 2 && i <= NN - 2);
    bool jcol = (j >= 2 && j <= NN - 2);

#define HYv(r, c) Hyb[(r) * HYW + (c)]
#define HXv(r, c) Hxb[(r) * HXW + (c)]

    if (irow && jcol) {
        // s1 interior: sum_{a=0..3,b2=0..2} Hy[i-2+a, j-2+b2] * M[b2][a]
        s1 += m.M00 * HYv(i - 2, j - 2) + m.M20 * HYv(i - 2, j);
        s1 += m.M01 * HYv(i - 1, j - 2) + m.M11 * HYv(i - 1, j - 1) + m.M21 * HYv(i - 1, j);
        s1 += m.M02 * HYv(i,     j - 2) + m.M22 * HYv(i,     j);
        s1 += m.M03 * HYv(i + 1, j - 2) + m.M23 * HYv(i + 1, j);
        // s2 interior: sum_{b2=0..2,a=0..3} Hx[i-2+b2, j-2+a] * M[b2][a]
        s2 += m.M00 * HXv(i - 2, j - 2) + m.M01 * HXv(i - 2, j - 1)
            + m.M02 * HXv(i - 2, j)     + m.M03 * HXv(i - 2, j + 1);
        s2 += m.M11 * HXv(i - 1, j - 1);
        s2 += m.M20 * HXv(i,     j - 2) + m.M21 * HXv(i,     j - 1)
            + m.M22 * HXv(i,     j)     + m.M23 * HXv(i,     j + 1);
    }

    // s1 KF term: rows i>=1, cols j<=NN-5, uses Hy[i-1, j..j+3]
    if (i >= 1 && j <= NN - 5) {
        s1 += KF0 * HYv(i - 1, j)     + KF1 * HYv(i - 1, j + 1)
            + KF2 * HYv(i - 1, j + 2) + KF3 * HYv(i - 1, j + 3);
    }
    // s1 KB term: rows i<=NN-1, cols j>=5, uses Hy[i, j-5..j-2]
    if (i <= NN - 1 && j >= 5) {
        s1 += KB0 * HYv(i, j - 5) + KB1 * HYv(i, j - 4)
            + KB2 * HYv(i, j - 3) + KB3 * HYv(i, j - 2);
    }
    // s1 FU band: 2<=i<=NN-2, 1<=j<=2, Hy[i-1, j-1..j+2] * [-1,3,-3,1]
    if (irow && j >= 1 && j <= 2) {
        s1 += -HYv(i - 1, j - 1) + 3.0f * HYv(i - 1, j)
              - 3.0f * HYv(i - 1, j + 1) + HYv(i - 1, j + 2);
    }
    // s1 FD band: 2<=i<=NN-2, NN-2<=j<=NN-1, Hy[i, j-4..j-1] * [1,-3,3,-1]
    if (irow && j >= NN - 2 && j <= NN - 1) {
        s1 += HYv(i, j - 4) - 3.0f * HYv(i, j - 3)
            + 3.0f * HYv(i, j - 2) - HYv(i, j - 1);
    }

    // s2 KF term: cols j>=1, rows i<=NN-5, uses Hx[i..i+3, j-1]
    if (j >= 1 && i <= NN - 5) {
        s2 += KF0 * HXv(i, j - 1)     + KF1 * HXv(i + 1, j - 1)
            + KF2 * HXv(i + 2, j - 1) + KF3 * HXv(i + 3, j - 1);
    }
    // s2 KB term: cols j<=NN-1, rows i>=5, uses Hx[i-5..i-2, j]
    if (j <= NN - 1 && i >= 5) {
        s2 += KB0 * HXv(i - 5, j) + KB1 * HXv(i - 4, j)
            + KB2 * HXv(i - 3, j) + KB3 * HXv(i - 2, j);
    }
    // s2 FU band: 1<=i<=2, 2<=j<=NN-2, Hx[i-1..i+2, j-1] * [-1,3,-3,1]
    if (jcol && i >= 1 && i <= 2) {
        s2 += -HXv(i - 1, j - 1) + 3.0f * HXv(i, j - 1)
              - 3.0f * HXv(i + 1, j - 1) + HXv(i + 2, j - 1);
    }
    // s2 FD band: NN-2<=i<=NN-1, 2<=j<=NN-2, Hx[i-4..i-1, j] * [1,-3,3,-1]
    if (jcol && i >= NN - 2 && i <= NN - 1) {
        s2 += HXv(i - 4, j) - 3.0f * HXv(i - 3, j)
            + 3.0f * HXv(i - 2, j) - HXv(i - 1, j);
    }

#undef HYv
#undef HXv

    Eo[b * EN + i * EW + j] = Eb[i * EW + j] + CFLF * (s1 - s2);
}

// ---------------------------------------------------------------------------
// Faraday Hx: Hx_out[i,j] = Hx[i,j] - CFL*s3,  i in [0,NN-2], j in [0,NN-1]
// ---------------------------------------------------------------------------
__global__ void k_faraday_x(const float* __restrict__ E,
                            const float* __restrict__ Hx,
                            const float* __restrict__ sb,
                            const float* __restrict__ sd,
                            const float* __restrict__ sg,
                            float* __restrict__ Hxo)
{
    int j = blockIdx.x * blockDim.x + threadIdx.x;
    int i = blockIdx.y * blockDim.y + threadIdx.y;
    if (i >= HXH || j >= HXW) return;
    int b = blockIdx.z;

    const float* Eb  = E  + b * EN;
    const float* Hxb = Hx + b * HXN;

    MCoef m = make_M(sb, sd, sg);

#define Ev(r, c) Eb[(r) * EW + (c)]

    float s3 = 0.0f;
    if (j >= 1 && j <= NN - 2) {
        // sum_{b2=0..2,a=0..3} E[i+b2, j-1+a] * M[b2][a]
        s3 += m.M00 * Ev(i,     j - 1) + m.M01 * Ev(i,     j)
            + m.M02 * Ev(i,     j + 1) + m.M03 * Ev(i,     j + 2);
        s3 += m.M11 * Ev(i + 1, j);
        s3 += m.M20 * Ev(i + 2, j - 1) + m.M21 * Ev(i + 2, j)
            + m.M22 * Ev(i + 2, j + 1) + m.M23 * Ev(i + 2, j + 2);
    }
    // KEF: i<=NN-4, E[i+1..i+3, j] * [-1.5, 2, -0.5]
    if (i <= NN - 4) {
        s3 += -1.5f * Ev(i + 1, j) + 2.0f * Ev(i + 2, j) - 0.5f * Ev(i + 3, j);
    }
    // KEB: i>=2, E[i-1..i+1, j+1] * [0.5, -2, 1.5]
    if (i >= 2) {
        s3 += 0.5f * Ev(i - 1, j + 1) - 2.0f * Ev(i, j + 1) + 1.5f * Ev(i + 1, j + 1);
    }
#undef Ev

    Hxo[b * HXN + i * HXW + j] = Hxb[i * HXW + j] - CFLF * s3;
}

// ---------------------------------------------------------------------------
// Faraday Hy: Hy_out[i,j] = Hy[i,j] + CFL*s4,  i in [0,NN-1], j in [0,NN-2]
// ---------------------------------------------------------------------------
__global__ void k_faraday_y(const float* __restrict__ E,
                            const float* __restrict__ Hy,
                            const float* __restrict__ sb,
                            const float* __restrict__ sd,
                            const float* __restrict__ sg,
                            float* __restrict__ Hyo)
{
    int j = blockIdx.x * blockDim.x + threadIdx.x;
    int i = blockIdx.y * blockDim.y + threadIdx.y;
    if (i >= HYH || j >= HYW) return;
    int b = blockIdx.z;

    const float* Eb  = E  + b * EN;
    const float* Hyb = Hy + b * HYN;

    MCoef m = make_M(sb, sd, sg);

#define Ev(r, c) Eb[(r) * EW + (c)]

    float s4 = 0.0f;
    if (i >= 1 && i <= NN - 2) {
        // sum_{a=0..3,b2=0..2} E[i-1+a, j+b2] * M[b2][a]
        s4 += m.M00 * Ev(i - 1, j) + m.M20 * Ev(i - 1, j + 2);
        s4 += m.M01 * Ev(i,     j) + m.M11 * Ev(i, j + 1) + m.M21 * Ev(i, j + 2);
        s4 += m.M02 * Ev(i + 1, j) + m.M22 * Ev(i + 1, j + 2);
        s4 += m.M03 * Ev(i + 2, j) + m.M23 * Ev(i + 2, j + 2);
    }
    // KEF^T: j<=NN-4, E[i, j+1..j+3] * [-1.5, 2, -0.5]
    if (j <= NN - 4) {
        s4 += -1.5f * Ev(i, j + 1) + 2.0f * Ev(i, j + 2) - 0.5f * Ev(i, j + 3);
    }
    // KEB^T: j>=2, E[i+1, j-1..j+1] * [0.5, -2, 1.5]
    if (j >= 2) {
        s4 += 0.5f * Ev(i + 1, j - 1) - 2.0f * Ev(i + 1, j) + 1.5f * Ev(i + 1, j + 1);
    }
#undef Ev

    Hyo[b * HYN + i * HYW + j] = Hyb[i * HYW + j] + CFLF * s4;
}

// ---------------------------------------------------------------------------
extern "C" void kernel_launch(void* const* d_in, const int* in_sizes, int n_in,
                              void* d_out, int out_size)
{
    const float* E  = (const float*)d_in[0];
    const float* Hx = (const float*)d_in[1];
    const float* Hy = (const float*)d_in[2];
    const float* sb = (const float*)d_in[3];
    const float* sd = (const float*)d_in[4];
    const float* sg = (const float*)d_in[5];
    float* out = (float*)d_out;

    const int STEP = BB * (EN + HXN + HYN);

    dim3 blk(32, 8, 1);
    dim3 gE((EW + 31) / 32, (EW + 7) / 8, BB);
    dim3 gX((HXW + 31) / 32, (HXH + 7) / 8, BB);
    dim3 gY((HYW + 31) / 32, (HYH + 7) / 8, BB);

    for (int k = 0; k < 3; k++) {
        float* Eo  = out + k * STEP;
        float* Hxo = Eo + BB * EN;
        float* Hyo = Hxo + BB * HXN;

        k_amper<<<gE, blk>>>(E, Hx, Hy, sb, sd, sg, Eo);
        k_faraday_x<<<gX, blk>>>(Eo, Hx, sb, sd, sg, Hxo);
        k_faraday_y<<<gY, blk>>>(Eo, Hy, sb, sd, sg, Hyo);

        E = Eo; Hx = Hxo; Hy = Hyo;
    }
}

// round 2
// speedup vs baseline: 1.2086x; 1.2086x over previous
#include <cuda_runtime.h>

// Problem constants (fixed: N=2048, B=2)
#define NN   2048
#define BB   2
#define EW   (NN + 1)            // 2049
#define HXH  (NN - 1)            // 2047
#define HXW  (NN)                // 2048
#define HYH  (NN)                // 2048
#define HYW  (NN - 1)            // 2047
#define EN   (EW * EW)
#define HXN  (HXH * HXW)
#define HYN  (HYH * HYW)
#define CFLF 0.35f

#define KF0 (-11.0f / 6.0f)
#define KF1 (3.0f)
#define KF2 (-1.5f)
#define KF3 (1.0f / 3.0f)
#define KB0 (-1.0f / 3.0f)
#define KB1 (1.5f)
#define KB2 (-3.0f)
#define KB3 (11.0f / 6.0f)

struct MCoef {
    float M00, M01, M02, M03, M11, M20, M21, M22, M23;
};

__device__ __forceinline__ MCoef make_M(const float* sb, const float* sd, const float* sg) {
    float beta = *sb, delta = *sd, gamma = *sg;
    MCoef m;
    m.M00 = -0.25f * beta + 0.1f * gamma;
    m.M01 =  0.25f * beta + delta - 0.5f - 0.1f * gamma;
    m.M02 =  0.25f * beta - 0.1f * gamma;
    m.M03 = -0.25f * beta + 0.1f * gamma;
    m.M11 = -2.0f * delta;
    m.M20 =  0.25f * beta - 0.1f * gamma;
    m.M21 = -0.25f * beta + delta + 0.5f + 0.1f * gamma;
    m.M22 = -0.25f * beta - 0.1f * gamma;
    m.M23 =  0.25f * beta + 0.1f * gamma;
    return m;
}

// ---------------------------------------------------------------------------
// Generic (boundary) amper point: returns s1 - s2 at (i,j). Caller guarantees
// 0<=i<=NN, 0<=j<=NN.
// ---------------------------------------------------------------------------
__device__ float amper_point(const float* __restrict__ Hxb,
                             const float* __restrict__ Hyb,
                             int i, int j, const MCoef& m)
{
    float s1 = 0.0f, s2 = 0.0f;
    bool irow = (i >= 2 && i <= NN - 2);
    bool jcol = (j >= 2 && j <= NN - 2);

#define HYv(r, c) Hyb[(r) * HYW + (c)]
#define HXv(r, c) Hxb[(r) * HXW + (c)]
    if (irow && jcol) {
        s1 += m.M00 * HYv(i - 2, j - 2) + m.M20 * HYv(i - 2, j);
        s1 += m.M01 * HYv(i - 1, j - 2) + m.M11 * HYv(i - 1, j - 1) + m.M21 * HYv(i - 1, j);
        s1 += m.M02 * HYv(i,     j - 2) + m.M22 * HYv(i,     j);
        s1 += m.M03 * HYv(i + 1, j - 2) + m.M23 * HYv(i + 1, j);
        s2 += m.M00 * HXv(i - 2, j - 2) + m.M01 * HXv(i - 2, j - 1)
            + m.M02 * HXv(i - 2, j)     + m.M03 * HXv(i - 2, j + 1);
        s2 += m.M11 * HXv(i - 1, j - 1);
        s2 += m.M20 * HXv(i,     j - 2) + m.M21 * HXv(i,     j - 1)
            + m.M22 * HXv(i,     j)     + m.M23 * HXv(i,     j + 1);
    }
    if (i >= 1 && j <= NN - 5) {
        s1 += KF0 * HYv(i - 1, j)     + KF1 * HYv(i - 1, j + 1)
            + KF2 * HYv(i - 1, j + 2) + KF3 * HYv(i - 1, j + 3);
    }
    if (i <= NN - 1 && j >= 5) {
        s1 += KB0 * HYv(i, j - 5) + KB1 * HYv(i, j - 4)
            + KB2 * HYv(i, j - 3) + KB3 * HYv(i, j - 2);
    }
    if (irow && j >= 1 && j <= 2) {
        s1 += -HYv(i - 1, j - 1) + 3.0f * HYv(i - 1, j)
              - 3.0f * HYv(i - 1, j + 1) + HYv(i - 1, j + 2);
    }
    if (irow && j >= NN - 2 && j <= NN - 1) {
        s1 += HYv(i, j - 4) - 3.0f * HYv(i, j - 3)
            + 3.0f * HYv(i, j - 2) - HYv(i, j - 1);
    }
    if (j >= 1 && i <= NN - 5) {
        s2 += KF0 * HXv(i, j - 1)     + KF1 * HXv(i + 1, j - 1)
            + KF2 * HXv(i + 2, j - 1) + KF3 * HXv(i + 3, j - 1);
    }
    if (j <= NN - 1 && i >= 5) {
        s2 += KB0 * HXv(i - 5, j) + KB1 * HXv(i - 4, j)
            + KB2 * HXv(i - 3, j) + KB3 * HXv(i - 2, j);
    }
    if (jcol && i >= 1 && i <= 2) {
        s2 += -HXv(i - 1, j - 1) + 3.0f * HXv(i, j - 1)
              - 3.0f * HXv(i + 1, j - 1) + HXv(i + 2, j - 1);
    }
    if (jcol && i >= NN - 2 && i <= NN - 1) {
        s2 += HXv(i - 4, j) - 3.0f * HXv(i - 3, j)
            + 3.0f * HXv(i - 2, j) - HXv(i - 1, j);
    }
#undef HYv
#undef HXv
    return s1 - s2;
}

// ---------------------------------------------------------------------------
// Amper kernel, 4 outputs per thread along j
// ---------------------------------------------------------------------------
__global__ __launch_bounds__(256)
void k_amper(const float* __restrict__ E,
             const float* __restrict__ Hx,
             const float* __restrict__ Hy,
             const float* __restrict__ sb,
             const float* __restrict__ sd,
             const float* __restrict__ sg,
             float* __restrict__ Eo)
{
    int j0 = (blockIdx.x * blockDim.x + threadIdx.x) * 4;
    int i  = blockIdx.y * blockDim.y + threadIdx.y;
    if (i >= EW || j0 >= EW) return;
    int b = blockIdx.z;

    const float* Eb  = E  + b * EN;
    const float* Hxb = Hx + b * HXN;
    const float* Hyb = Hy + b * HYN;
    float* Eob = Eo + b * EN;

    MCoef m = make_M(sb, sd, sg);

    bool fast = (i >= 5) && (i <= NN - 5) && (j0 >= 5) && (j0 + 3 <= NN - 5);
    if (fast) {
        const int j = j0;
        float s1[4] = {0, 0, 0, 0}, s2[4] = {0, 0, 0, 0};
        const float cM21KF0 = m.M21 + KF0;
        const float cM02KB3 = m.M02 + KB3;

        // ---- Hy rows ----
        {   // row i-2: a[t] = Hy(i-2, j-2+t), t=0..5
            const float* r = Hyb + (i - 2) * HYW + (j - 2);
            float a[6];
            #pragma unroll
            for (int t = 0; t < 6; t++) a[t] = r[t];
            #pragma unroll
            for (int q = 0; q < 4; q++) s1[q] += m.M00 * a[q] + m.M20 * a[q + 2];
        }
        {   // row i-1: b[t] = Hy(i-1, j-2+t), t=0..8
            const float* r = Hyb + (i - 1) * HYW + (j - 2);
            float a[9];
            #pragma unroll
            for (int t = 0; t < 9; t++) a[t] = r[t];
            #pragma unroll
            for (int q = 0; q < 4; q++) {
                s1[q] += m.M01 * a[q] + m.M11 * a[q + 1] + cM21KF0 * a[q + 2]
                       + KF1 * a[q + 3] + KF2 * a[q + 4] + KF3 * a[q + 5];
            }
        }
        {   // row i: c[t] = Hy(i, j-5+t), t=0..8
            const float* r = Hyb + i * HYW + (j - 5);
            float a[9];
            #pragma unroll
            for (int t = 0; t < 9; t++) a[t] = r[t];
            #pragma unroll
            for (int q = 0; q < 4; q++) {
                s1[q] += KB0 * a[q] + KB1 * a[q + 1] + KB2 * a[q + 2]
                       + cM02KB3 * a[q + 3] + m.M22 * a[q + 5];
            }
        }
        {   // row i+1
            const float* r = Hyb + (i + 1) * HYW + (j - 2);
            float a[6];
            #pragma unroll
            for (int t = 0; t < 6; t++) a[t] = r[t];
            #pragma unroll
            for (int q = 0; q < 4; q++) s1[q] += m.M03 * a[q] + m.M23 * a[q + 2];
        }

        // ---- Hx rows ----
        {   // rows i-5..i-3: col j..j+3 with KB0..KB2
            const float* r5 = Hxb + (i - 5) * HXW + j;
            const float* r4 = Hxb + (i - 4) * HXW + j;
            const float* r3 = Hxb + (i - 3) * HXW + j;
            #pragma unroll
            for (int q = 0; q < 4; q++)
                s2[q] += KB0 * r5[q] + KB1 * r4[q] + KB2 * r3[q];
        }
        {   // row i-2: f[t] = Hx(i-2, j-2+t), t=0..6
            const float* r = Hxb + (i - 2) * HXW + (j - 2);
            float a[7];
            #pragma unroll
            for (int t = 0; t < 7; t++) a[t] = r[t];
            #pragma unroll
            for (int q = 0; q < 4; q++)
                s2[q] += m.M00 * a[q] + m.M01 * a[q + 1] + cM02KB3 * a[q + 2] + m.M03 * a[q + 3];
        }
        {   // row i-1: g[t] = Hx(i-1, j-1+t), t=0..3
            const float* r = Hxb + (i - 1) * HXW + (j - 1);
            #pragma unroll
            for (int q = 0; q < 4; q++) s2[q] += m.M11 * r[q];
        }
        {   // row i: h[t] = Hx(i, j-2+t), t=0..6
            const float* r = Hxb + i * HXW + (j - 2);
            float a[7];
            #pragma unroll
            for (int t = 0; t < 7; t++) a[t] = r[t];
            #pragma unroll
            for (int q = 0; q < 4; q++)
                s2[q] += m.M20 * a[q] + cM21KF0 * a[q + 1] + m.M22 * a[q + 2] + m.M23 * a[q + 3];
        }
        {   // rows i+1..i+3: col j-1..j+2 with KF1..KF3
            const float* r1 = Hxb + (i + 1) * HXW + (j - 1);
            const float* r2 = Hxb + (i + 2) * HXW + (j - 1);
            const float* r3 = Hxb + (i + 3) * HXW + (j - 1);
            #pragma unroll
            for (int q = 0; q < 4; q++)
                s2[q] += KF1 * r1[q] + KF2 * r2[q] + KF3 * r3[q];
        }

        const float* er = Eb + i * EW + j;
        float* wr = Eob + i * EW + j;
        #pragma unroll
        for (int q = 0; q < 4; q++)
            wr[q] = er[q] + CFLF * (s1[q] - s2[q]);
    } else {
        #pragma unroll
        for (int q = 0; q < 4; q++) {
            int j = j0 + q;
            if (j > NN) break;
            float d = amper_point(Hxb, Hyb, i, j, m);
            Eob[i * EW + j] = Eb[i * EW + j] + CFLF * d;
        }
    }
}

// ---------------------------------------------------------------------------
// Generic faraday point helpers
// ---------------------------------------------------------------------------
__device__ float faraday_s3(const float* __restrict__ Eb, int i, int j, const MCoef& m)
{
#define Ev(r, c) Eb[(r) * EW + (c)]
    float s3 = 0.0f;
    if (j >= 1 && j <= NN - 2) {
        s3 += m.M00 * Ev(i,     j - 1) + m.M01 * Ev(i,     j)
            + m.M02 * Ev(i,     j + 1) + m.M03 * Ev(i,     j + 2);
        s3 += m.M11 * Ev(i + 1, j);
        s3 += m.M20 * Ev(i + 2, j - 1) + m.M21 * Ev(i + 2, j)
            + m.M22 * Ev(i + 2, j + 1) + m.M23 * Ev(i + 2, j + 2);
    }
    if (i <= NN - 4)
        s3 += -1.5f * Ev(i + 1, j) + 2.0f * Ev(i + 2, j) - 0.5f * Ev(i + 3, j);
    if (i >= 2)
        s3 += 0.5f * Ev(i - 1, j + 1) - 2.0f * Ev(i, j + 1) + 1.5f * Ev(i + 1, j + 1);
#undef Ev
    return s3;
}

__device__ float faraday_s4(const float* __restrict__ Eb, int i, int j, const MCoef& m)
{
#define Ev(r, c) Eb[(r) * EW + (c)]
    float s4 = 0.0f;
    if (i >= 1 && i <= NN - 2) {
        s4 += m.M00 * Ev(i - 1, j) + m.M20 * Ev(i - 1, j + 2);
        s4 += m.M01 * Ev(i,     j) + m.M11 * Ev(i, j + 1) + m.M21 * Ev(i, j + 2);
        s4 += m.M02 * Ev(i + 1, j) + m.M22 * Ev(i + 1, j + 2);
        s4 += m.M03 * Ev(i + 2, j) + m.M23 * Ev(i + 2, j + 2);
    }
    if (j <= NN - 4)
        s4 += -1.5f * Ev(i, j + 1) + 2.0f * Ev(i, j + 2) - 0.5f * Ev(i, j + 3);
    if (j >= 2)
        s4 += 0.5f * Ev(i + 1, j - 1) - 2.0f * Ev(i + 1, j) + 1.5f * Ev(i + 1, j + 1);
#undef Ev
    return s4;
}

// ---------------------------------------------------------------------------
// Fused faraday: computes Hx_out and Hy_out, 4 j per thread, shared E reads
// ---------------------------------------------------------------------------
__global__ __launch_bounds__(256)
void k_faraday(const float* __restrict__ E,
               const float* __restrict__ Hx,
               const float* __restrict__ Hy,
               const float* __restrict__ sb,
               const float* __restrict__ sd,
               const float* __restrict__ sg,
               float* __restrict__ Hxo,
               float* __restrict__ Hyo)
{
    int j0 = (blockIdx.x * blockDim.x + threadIdx.x) * 4;
    int i  = blockIdx.y * blockDim.y + threadIdx.y;
    if (i >= NN || j0 >= NN) return;
    int b = blockIdx.z;

    const float* Eb  = E  + b * EN;
    const float* Hxb = Hx + b * HXN;
    const float* Hyb = Hy + b * HYN;
    float* Hxob = Hxo + b * HXN;
    float* Hyob = Hyo + b * HYN;

    MCoef m = make_M(sb, sd, sg);

    bool fast = (i >= 2) && (i <= NN - 4) && (j0 >= 2) && (j0 + 3 <= NN - 7 + 3) && (j0 + 3 <= NN - 4);
    if (fast) {
        const int j = j0;
        float s3[4] = {0, 0, 0, 0}, s4[4] = {0, 0, 0, 0};

        {   // row i-1: a[t] = E(i-1, j+t), t=0..5
            const float* r = Eb + (i - 1) * EW + j;
            float a[6];
            #pragma unroll
            for (int t = 0; t < 6; t++) a[t] = r[t];
            #pragma unroll
            for (int q = 0; q < 4; q++) {
                s3[q] += 0.5f * a[q + 1];
                s4[q] += m.M00 * a[q] + m.M20 * a[q + 2];
            }
        }
        {   // row i: b[t] = E(i, j-1+t), t=0..7
            const float* r = Eb + i * EW + (j - 1);
            float a[8];
            #pragma unroll
            for (int t = 0; t < 8; t++) a[t] = r[t];
            const float c3_2 = m.M02 - 2.0f;     // s3 coeff at b[q+2]
            const float c4_2 = m.M11 - 1.5f;     // s4 coeff at b[q+2]
            const float c4_3 = m.M21 + 2.0f;     // s4 coeff at b[q+3]
            #pragma unroll
            for (int q = 0; q < 4; q++) {
                s3[q] += m.M00 * a[q] + m.M01 * a[q + 1] + c3_2 * a[q + 2] + m.M03 * a[q + 3];
                s4[q] += m.M01 * a[q + 1] + c4_2 * a[q + 2] + c4_3 * a[q + 3] - 0.5f * a[q + 4];
            }
        }
        {   // row i+1: c[t] = E(i+1, j-1+t), t=0..6
            const float* r = Eb + (i + 1) * EW + (j - 1);
            float a[7];
            #pragma unroll
            for (int t = 0; t < 7; t++) a[t] = r[t];
            const float c3_1 = m.M11 - 1.5f;     // s3 coeff at c[q+1]
            const float c4_1 = m.M02 - 2.0f;     // s4 coeff at c[q+1]
            #pragma unroll
            for (int q = 0; q < 4; q++) {
                s3[q] += c3_1 * a[q + 1] + 1.5f * a[q + 2];
                s4[q] += 0.5f * a[q] + c4_1 * a[q + 1] + 1.5f * a[q + 2] + m.M22 * a[q + 3];
            }
        }
        {   // row i+2: d[t] = E(i+2, j-1+t), t=0..6
            const float* r = Eb + (i + 2) * EW + (j - 1);
            float a[7];
            #pragma unroll
            for (int t = 0; t < 7; t++) a[t] = r[t];
            const float c3_1 = m.M21 + 2.0f;
            #pragma unroll
            for (int q = 0; q < 4; q++) {
                s3[q] += m.M20 * a[q] + c3_1 * a[q + 1] + m.M22 * a[q + 2] + m.M23 * a[q + 3];
                s4[q] += m.M03 * a[q + 1] + m.M23 * a[q + 3];
            }
        }
        {   // row i+3: e[t] = E(i+3, j+t), t=0..3
            const float* r = Eb + (i + 3) * EW + j;
            #pragma unroll
            for (int q = 0; q < 4; q++) s3[q] += -0.5f * r[q];
        }

        // stores (i <= NN-4 < HXH so Hx row valid; j+3 <= NN-4 < widths)
        const float* hxr = Hxb + i * HXW + j;
        const float* hyr = Hyb + i * HYW + j;
        float* hxw = Hxob + i * HXW + j;
        float* hyw = Hyob + i * HYW + j;
        #pragma unroll
        for (int q = 0; q < 4; q++) {
            hxw[q] = hxr[q] - CFLF * s3[q];
            hyw[q] = hyr[q] + CFLF * s4[q];
        }
    } else {
        #pragma unroll
        for (int q = 0; q < 4; q++) {
            int j = j0 + q;
            if (j >= NN) break;
            if (i < HXH && j < HXW) {
                float s3 = faraday_s3(Eb, i, j, m);
                Hxob[i * HXW + j] = Hxb[i * HXW + j] - CFLF * s3;
            }
            if (i < HYH && j < HYW) {
                float s4 = faraday_s4(Eb, i, j, m);
                Hyob[i * HYW + j] = Hyb[i * HYW + j] + CFLF * s4;
            }
        }
    }
}

// ---------------------------------------------------------------------------
extern "C" void kernel_launch(void* const* d_in, const int* in_sizes, int n_in,
                              void* d_out, int out_size)
{
    const float* E  = (const float*)d_in[0];
    const float* Hx = (const float*)d_in[1];
    const float* Hy = (const float*)d_in[2];
    const float* sb = (const float*)d_in[3];
    const float* sd = (const float*)d_in[4];
    const float* sg = (const float*)d_in[5];
    float* out = (float*)d_out;

    const int STEP = BB * (EN + HXN + HYN);

    dim3 blk(32, 8, 1);
    // amper: 513 strips of 4 cover 2049; rows 2049
    dim3 gE((513 + 31) / 32, (EW + 7) / 8, BB);
    // faraday: 512 strips cover 2048; rows 2048
    dim3 gF((512 + 31) / 32, (NN + 7) / 8, BB);

    for (int k = 0; k < 3; k++) {
        float* Eo  = out + k * STEP;
        float* Hxo = Eo + BB * EN;
        float* Hyo = Hxo + BB * HXN;

        k_amper<<<gE, blk>>>(E, Hx, Hy, sb, sd, sg, Eo);
        k_faraday<<<gF, blk>>>(Eo, Hx, Hy, sb, sd, sg, Hxo, Hyo);

        E = Eo; Hx = Hxo; Hy = Hyo;
    }
}

// round 3
// speedup vs baseline: 1.7458x; 1.4444x over previous
#include <cuda_runtime.h>

// Problem constants (fixed: N=2048, B=2)
#define NN   2048
#define BB   2
#define EW   (NN + 1)            // 2049
#define HXH  (NN - 1)            // 2047
#define HXW  (NN)                // 2048
#define HYH  (NN)                // 2048
#define HYW  (NN - 1)            // 2047
#define EN   (EW * EW)
#define HXN  (HXH * HXW)
#define HYN  (HYH * HYW)
#define CFLF 0.35f

#define KF0 (-11.0f / 6.0f)
#define KF1 (3.0f)
#define KF2 (-1.5f)
#define KF3 (1.0f / 3.0f)
#define KB0 (-1.0f / 3.0f)
#define KB1 (1.5f)
#define KB2 (-3.0f)
#define KB3 (11.0f / 6.0f)

struct MCoef {
    float M00, M01, M02, M03, M11, M20, M21, M22, M23;
};

__device__ __forceinline__ MCoef make_M(const float* sb, const float* sd, const float* sg) {
    float beta = *sb, delta = *sd, gamma = *sg;
    MCoef m;
    m.M00 = -0.25f * beta + 0.1f * gamma;
    m.M01 =  0.25f * beta + delta - 0.5f - 0.1f * gamma;
    m.M02 =  0.25f * beta - 0.1f * gamma;
    m.M03 = -0.25f * beta + 0.1f * gamma;
    m.M11 = -2.0f * delta;
    m.M20 =  0.25f * beta - 0.1f * gamma;
    m.M21 = -0.25f * beta + delta + 0.5f + 0.1f * gamma;
    m.M22 = -0.25f * beta - 0.1f * gamma;
    m.M23 =  0.25f * beta + 0.1f * gamma;
    return m;
}

// ---------------------------------------------------------------------------
// Vectorized window load: out[t] = buf[idx + t], t = 0..W-1, using aligned
// LDG.128. buf must be 16B-aligned; idx arbitrary. Skew (idx&3) is
// warp-uniform at all call sites (idx varies across lanes by multiples of 4).
// May read up to 3 floats beyond [idx, idx+W) — callers guarantee these stay
// inside the allocation.
// ---------------------------------------------------------------------------
template<int W>
__device__ __forceinline__ void load_win(const float* __restrict__ buf, int idx,
                                         float* __restrict__ out)
{
    const int g0 = idx & ~3;
    const int k = idx & 3;
    const float4* p = reinterpret_cast<const float4*>(buf + g0);
#define LW_CASE(K)                                                         \
    {                                                                      \
        constexpr int NV = (W + (K) + 3) / 4;                              \
        float f[NV * 4];                                                   \
        _Pragma("unroll")                                                  \
        for (int t = 0; t < NV; t++)                                       \
            *reinterpret_cast<float4*>(f + 4 * t) = p[t];                  \
        _Pragma("unroll")                                                  \
        for (int t = 0; t < W; t++) out[t] = f[t + (K)];                   \
    }                                                                      \
    break;
    switch (k) {
        case 0: LW_CASE(0)
        case 1: LW_CASE(1)
        case 2: LW_CASE(2)
        default: switch (k) { case 2: break; case 3: LW_CASE(3) }
    }
#undef LW_CASE
}

// ---------------------------------------------------------------------------
// Generic (boundary) amper point: returns s1 - s2 at (i,j).
// ---------------------------------------------------------------------------
__device__ float amper_point(const float* __restrict__ Hxb,
                             const float* __restrict__ Hyb,
                             int i, int j, const MCoef& m)
{
    float s1 = 0.0f, s2 = 0.0f;
    bool irow = (i >= 2 && i <= NN - 2);
    bool jcol = (j >= 2 && j <= NN - 2);

#define HYv(r, c) Hyb[(r) * HYW + (c)]
#define HXv(r, c) Hxb[(r) * HXW + (c)]
    if (irow && jcol) {
        s1 += m.M00 * HYv(i - 2, j - 2) + m.M20 * HYv(i - 2, j);
        s1 += m.M01 * HYv(i - 1, j - 2) + m.M11 * HYv(i - 1, j - 1) + m.M21 * HYv(i - 1, j);
        s1 += m.M02 * HYv(i,     j - 2) + m.M22 * HYv(i,     j);
        s1 += m.M03 * HYv(i + 1, j - 2) + m.M23 * HYv(i + 1, j);
        s2 += m.M00 * HXv(i - 2, j - 2) + m.M01 * HXv(i - 2, j - 1)
            + m.M02 * HXv(i - 2, j)     + m.M03 * HXv(i - 2, j + 1);
        s2 += m.M11 * HXv(i - 1, j - 1);
        s2 += m.M20 * HXv(i,     j - 2) + m.M21 * HXv(i,     j - 1)
            + m.M22 * HXv(i,     j)     + m.M23 * HXv(i,     j + 1);
    }
    if (i >= 1 && j <= NN - 5) {
        s1 += KF0 * HYv(i - 1, j)     + KF1 * HYv(i - 1, j + 1)
            + KF2 * HYv(i - 1, j + 2) + KF3 * HYv(i - 1, j + 3);
    }
    if (i <= NN - 1 && j >= 5) {
        s1 += KB0 * HYv(i, j - 5) + KB1 * HYv(i, j - 4)
            + KB2 * HYv(i, j - 3) + KB3 * HYv(i, j - 2);
    }
    if (irow && j >= 1 && j <= 2) {
        s1 += -HYv(i - 1, j - 1) + 3.0f * HYv(i - 1, j)
              - 3.0f * HYv(i - 1, j + 1) + HYv(i - 1, j + 2);
    }
    if (irow && j >= NN - 2 && j <= NN - 1) {
        s1 += HYv(i, j - 4) - 3.0f * HYv(i, j - 3)
            + 3.0f * HYv(i, j - 2) - HYv(i, j - 1);
    }
    if (j >= 1 && i <= NN - 5) {
        s2 += KF0 * HXv(i, j - 1)     + KF1 * HXv(i + 1, j - 1)
            + KF2 * HXv(i + 2, j - 1) + KF3 * HXv(i + 3, j - 1);
    }
    if (j <= NN - 1 && i >= 5) {
        s2 += KB0 * HXv(i - 5, j) + KB1 * HXv(i - 4, j)
            + KB2 * HXv(i - 3, j) + KB3 * HXv(i - 2, j);
    }
    if (jcol && i >= 1 && i <= 2) {
        s2 += -HXv(i - 1, j - 1) + 3.0f * HXv(i, j - 1)
              - 3.0f * HXv(i + 1, j - 1) + HXv(i + 2, j - 1);
    }
    if (jcol && i >= NN - 2 && i <= NN - 1) {
        s2 += HXv(i - 4, j) - 3.0f * HXv(i - 3, j)
            + 3.0f * HXv(i - 2, j) - HXv(i - 1, j);
    }
#undef HYv
#undef HXv
    return s1 - s2;
}

// ---------------------------------------------------------------------------
// Amper kernel: 4 outputs per thread along j, j0 aligned to the E OUTPUT row
// so the store is a single STG.128. All inputs via base pointer + int offset
// (buffers change between d_in and d_out across steps).
// ---------------------------------------------------------------------------
__global__ __launch_bounds__(256)
void k_amper(const float* __restrict__ e_base,  int e_off,
             const float* __restrict__ hx_base, int hx_off,
             const float* __restrict__ hy_base, int hy_off,
             float* __restrict__ out_base,      int eo_off,
             const float* __restrict__ sb,
             const float* __restrict__ sd,
             const float* __restrict__ sg)
{
    int t = blockIdx.x * blockDim.x + threadIdx.x;
    int i = blockIdx.y * blockDim.y + threadIdx.y;
    if (i >= EW) return;
    int b = blockIdx.z;

    const int erow = eo_off + b * EN + i * EW;   // output row base (global idx)
    const int s = erow & 3;                      // warp-uniform skew
    const int j = 4 * t - s;                     // aligned output start col
    if (j + 3 < 0 || j > NN) return;

    MCoef m = make_M(sb, sd, sg);

    const int xb = hx_off + b * HXN;
    const int yb = hy_off + b * HYN;

    bool fast = (i >= 5) && (i <= NN - 5) && (j >= 5) && (j + 3 <= NN - 5);
    if (fast) {
        float s1[4] = {0, 0, 0, 0}, s2[4] = {0, 0, 0, 0};
        const float cM21KF0 = m.M21 + KF0;
        const float cM02KB3 = m.M02 + KB3;

        // ---- Hy rows ----
        {
            float A[6];
            load_win<6>(hy_base, yb + (i - 2) * HYW + (j - 2), A);
            #pragma unroll
            for (int q = 0; q < 4; q++) s1[q] += m.M00 * A[q] + m.M20 * A[q + 2];
        }
        {
            float A[9];
            load_win<9>(hy_base, yb + (i - 1) * HYW + (j - 2), A);
            #pragma unroll
            for (int q = 0; q < 4; q++)
                s1[q] += m.M01 * A[q] + m.M11 * A[q + 1] + cM21KF0 * A[q + 2]
                       + KF1 * A[q + 3] + KF2 * A[q + 4] + KF3 * A[q + 5];
        }
        {
            float A[9];
            load_win<9>(hy_base, yb + i * HYW + (j - 5), A);
            #pragma unroll
            for (int q = 0; q < 4; q++)
                s1[q] += KB0 * A[q] + KB1 * A[q + 1] + KB2 * A[q + 2]
                       + cM02KB3 * A[q + 3] + m.M22 * A[q + 5];
        }
        {
            float A[6];
            load_win<6>(hy_base, yb + (i + 1) * HYW + (j - 2), A);
            #pragma unroll
            for (int q = 0; q < 4; q++) s1[q] += m.M03 * A[q] + m.M23 * A[q + 2];
        }

        // ---- Hx rows ----
        {
            float R5[4], R4[4], R3[4];
            load_win<4>(hx_base, xb + (i - 5) * HXW + j, R5);
            load_win<4>(hx_base, xb + (i - 4) * HXW + j, R4);
            load_win<4>(hx_base, xb + (i - 3) * HXW + j, R3);
            #pragma unroll
            for (int q = 0; q < 4; q++)
                s2[q] += KB0 * R5[q] + KB1 * R4[q] + KB2 * R3[q];
        }
        {
            float A[7];
            load_win<7>(hx_base, xb + (i - 2) * HXW + (j - 2), A);
            #pragma unroll
            for (int q = 0; q < 4; q++)
                s2[q] += m.M00 * A[q] + m.M01 * A[q + 1] + cM02KB3 * A[q + 2] + m.M03 * A[q + 3];
        }
        {
            float A[4];
            load_win<4>(hx_base, xb + (i - 1) * HXW + (j - 1), A);
            #pragma unroll
            for (int q = 0; q < 4; q++) s2[q] += m.M11 * A[q];
        }
        {
            float A[7];
            load_win<7>(hx_base, xb + i * HXW + (j - 2), A);
            #pragma unroll
            for (int q = 0; q < 4; q++)
                s2[q] += m.M20 * A[q] + cM21KF0 * A[q + 1] + m.M22 * A[q + 2] + m.M23 * A[q + 3];
        }
        {
            float R1[4], R2[4], R3[4];
            load_win<4>(hx_base, xb + (i + 1) * HXW + (j - 1), R1);
            load_win<4>(hx_base, xb + (i + 2) * HXW + (j - 1), R2);
            load_win<4>(hx_base, xb + (i + 3) * HXW + (j - 1), R3);
            #pragma unroll
            for (int q = 0; q < 4; q++)
                s2[q] += KF1 * R1[q] + KF2 * R2[q] + KF3 * R3[q];
        }

        float Ein[4];
        load_win<4>(e_base, e_off + b * EN + i * EW + j, Ein);
        float4 w;
        w.x = Ein[0] + CFLF * (s1[0] - s2[0]);
        w.y = Ein[1] + CFLF * (s1[1] - s2[1]);
        w.z = Ein[2] + CFLF * (s1[2] - s2[2]);
        w.w = Ein[3] + CFLF * (s1[3] - s2[3]);
        *reinterpret_cast<float4*>(out_base + erow + j) = w;   // aligned by construction
    } else {
        const float* Eb  = e_base + e_off + b * EN;
        const float* Hxb = hx_base + xb;
        const float* Hyb = hy_base + yb;
        float* Eob = out_base + eo_off + b * EN;
        #pragma unroll
        for (int q = 0; q < 4; q++) {
            int jj = j + q;
            if (jj < 0 || jj > NN) continue;
            float d = amper_point(Hxb, Hyb, i, jj, m);
            Eob[i * EW + jj] = Eb[i * EW + jj] + CFLF * d;
        }
    }
}

// ---------------------------------------------------------------------------
// Generic faraday point helpers
// ---------------------------------------------------------------------------
__device__ float faraday_s3(const float* __restrict__ Eb, int i, int j, const MCoef& m)
{
#define Ev(r, c) Eb[(r) * EW + (c)]
    float s3 = 0.0f;
    if (j >= 1 && j <= NN - 2) {
        s3 += m.M00 * Ev(i,     j - 1) + m.M01 * Ev(i,     j)
            + m.M02 * Ev(i,     j + 1) + m.M03 * Ev(i,     j + 2);
        s3 += m.M11 * Ev(i + 1, j);
        s3 += m.M20 * Ev(i + 2, j - 1) + m.M21 * Ev(i + 2, j)
            + m.M22 * Ev(i + 2, j + 1) + m.M23 * Ev(i + 2, j + 2);
    }
    if (i <= NN - 4)
        s3 += -1.5f * Ev(i + 1, j) + 2.0f * Ev(i + 2, j) - 0.5f * Ev(i + 3, j);
    if (i >= 2)
        s3 += 0.5f * Ev(i - 1, j + 1) - 2.0f * Ev(i, j + 1) + 1.5f * Ev(i + 1, j + 1);
#undef Ev
    return s3;
}

__device__ float faraday_s4(const float* __restrict__ Eb, int i, int j, const MCoef& m)
{
#define Ev(r, c) Eb[(r) * EW + (c)]
    float s4 = 0.0f;
    if (i >= 1 && i <= NN - 2) {
        s4 += m.M00 * Ev(i - 1, j) + m.M20 * Ev(i - 1, j + 2);
        s4 += m.M01 * Ev(i,     j) + m.M11 * Ev(i, j + 1) + m.M21 * Ev(i, j + 2);
        s4 += m.M02 * Ev(i + 1, j) + m.M22 * Ev(i + 1, j + 2);
        s4 += m.M03 * Ev(i + 2, j) + m.M23 * Ev(i + 2, j + 2);
    }
    if (j <= NN - 4)
        s4 += -1.5f * Ev(i, j + 1) + 2.0f * Ev(i, j + 2) - 0.5f * Ev(i, j + 3);
    if (j >= 2)
        s4 += 0.5f * Ev(i + 1, j - 1) - 2.0f * Ev(i + 1, j) + 1.5f * Ev(i + 1, j + 1);
#undef Ev
    return s4;
}

// ---------------------------------------------------------------------------
// Fused faraday: Hx_out and Hy_out, 4 j per thread, j0 aligned to Hx OUTPUT
// (skew is constant for the whole launch since HXW and HXN are mult of 4).
// ---------------------------------------------------------------------------
__global__ __launch_bounds__(256)
void k_faraday(const float* __restrict__ e_base,  int e_off,
               const float* __restrict__ hx_base, int hx_off,
               const float* __restrict__ hy_base, int hy_off,
               float* __restrict__ out_base,      int hxo_off, int hyo_off,
               const float* __restrict__ sb,
               const float* __restrict__ sd,
               const float* __restrict__ sg)
{
    int t = blockIdx.x * blockDim.x + threadIdx.x;
    int i = blockIdx.y * blockDim.y + threadIdx.y;
    if (i >= NN) return;
    int b = blockIdx.z;

    const int sF = hxo_off & 3;      // launch-uniform skew for Hx output
    const int j = 4 * t - sF;
    if (j + 3 < 0 || j >= NN) return;

    MCoef m = make_M(sb, sd, sg);

    const int eb = e_off + b * EN;
    const int xb = hx_off + b * HXN;
    const int yb = hy_off + b * HYN;

    bool fast = (i >= 2) && (i <= NN - 4) && (j >= 2) && (j + 3 <= NN - 4);
    if (fast) {
        float s3[4] = {0, 0, 0, 0}, s4[4] = {0, 0, 0, 0};

        {
            float A[6];
            load_win<6>(e_base, eb + (i - 1) * EW + j, A);
            #pragma unroll
            for (int q = 0; q < 4; q++) {
                s3[q] += 0.5f * A[q + 1];
                s4[q] += m.M00 * A[q] + m.M20 * A[q + 2];
            }
        }
        {
            float A[8];
            load_win<8>(e_base, eb + i * EW + (j - 1), A);
            const float c3_2 = m.M02 - 2.0f;
            const float c4_2 = m.M11 - 1.5f;
            const float c4_3 = m.M21 + 2.0f;
            #pragma unroll
            for (int q = 0; q < 4; q++) {
                s3[q] += m.M00 * A[q] + m.M01 * A[q + 1] + c3_2 * A[q + 2] + m.M03 * A[q + 3];
                s4[q] += m.M01 * A[q + 1] + c4_2 * A[q + 2] + c4_3 * A[q + 3] - 0.5f * A[q + 4];
            }
        }
        {
            float A[7];
            load_win<7>(e_base, eb + (i + 1) * EW + (j - 1), A);
            const float c3_1 = m.M11 - 1.5f;
            const float c4_1 = m.M02 - 2.0f;
            #pragma unroll
            for (int q = 0; q < 4; q++) {
                s3[q] += c3_1 * A[q + 1] + 1.5f * A[q + 2];
                s4[q] += 0.5f * A[q] + c4_1 * A[q + 1] + 1.5f * A[q + 2] + m.M22 * A[q + 3];
            }
        }
        {
            float A[7];
            load_win<7>(e_base, eb + (i + 2) * EW + (j - 1), A);
            const float c3_1 = m.M21 + 2.0f;
            #pragma unroll
            for (int q = 0; q < 4; q++) {
                s3[q] += m.M20 * A[q] + c3_1 * A[q + 1] + m.M22 * A[q + 2] + m.M23 * A[q + 3];
                s4[q] += m.M03 * A[q + 1] + m.M23 * A[q + 3];
            }
        }
        {
            float A[4];
            load_win<4>(e_base, eb + (i + 3) * EW + j, A);
            #pragma unroll
            for (int q = 0; q < 4; q++) s3[q] += -0.5f * A[q];
        }

        float hxv[4], hyv[4];
        load_win<4>(hx_base, xb + i * HXW + j, hxv);
        load_win<4>(hy_base, yb + i * HYW + j, hyv);

        // Hx store: aligned STG.128 by construction
        float4 wx;
        wx.x = hxv[0] - CFLF * s3[0];
        wx.y = hxv[1] - CFLF * s3[1];
        wx.z = hxv[2] - CFLF * s3[2];
        wx.w = hxv[3] - CFLF * s3[3];
        *reinterpret_cast<float4*>(out_base + hxo_off + b * HXN + i * HXW + j) = wx;

        // Hy store: odd stride, scalar
        float* hyw = out_base + hyo_off + b * HYN + i * HYW + j;
        #pragma unroll
        for (int q = 0; q < 4; q++) hyw[q] = hyv[q] + CFLF * s4[q];
    } else {
        const float* Eb  = e_base + eb;
        const float* Hxb = hx_base + xb;
        const float* Hyb = hy_base + yb;
        float* Hxob = out_base + hxo_off + b * HXN;
        float* Hyob = out_base + hyo_off + b * HYN;
        #pragma unroll
        for (int q = 0; q < 4; q++) {
            int jj = j + q;
            if (jj < 0 || jj >= NN) continue;
            if (i < HXH && jj < HXW) {
                float s3 = faraday_s3(Eb, i, jj, m);
                Hxob[i * HXW + jj] = Hxb[i * HXW + jj] - CFLF * s3;
            }
            if (i < HYH && jj < HYW) {
                float s4 = faraday_s4(Eb, i, jj, m);
                Hyob[i * HYW + jj] = Hyb[i * HYW + jj] + CFLF * s4;
            }
        }
    }
}

// ---------------------------------------------------------------------------
extern "C" void kernel_launch(void* const* d_in, const int* in_sizes, int n_in,
                              void* d_out, int out_size)
{
    const float* sb = (const float*)d_in[3];
    const float* sd = (const float*)d_in[4];
    const float* sg = (const float*)d_in[5];
    float* out = (float*)d_out;

    const float* e_base  = (const float*)d_in[0]; int e_off  = 0;
    const float* hx_base = (const float*)d_in[1]; int hx_off = 0;
    const float* hy_base = (const float*)d_in[2]; int hy_off = 0;

    const int STEP = BB * (EN + HXN + HYN);

    dim3 blk(32, 8, 1);
    // 513 j-strips of 4 cover 2049 (+ up to 3 skew); rows 2049 / 2048
    dim3 gE((513 + 31) / 32, (EW + 7) / 8, BB);
    dim3 gF((513 + 31) / 32, (NN + 7) / 8, BB);

    for (int k = 0; k < 3; k++) {
        int eo_off  = k * STEP;
        int hxo_off = eo_off + BB * EN;
        int hyo_off = hxo_off + BB * HXN;

        k_amper<<<gE, blk>>>(e_base, e_off, hx_base, hx_off, hy_base, hy_off,
                             out, eo_off, sb, sd, sg);
        k_faraday<<<gF, blk>>>(out, eo_off, hx_base, hx_off, hy_base, hy_off,
                               out, hxo_off, hyo_off, sb, sd, sg);

        e_base = out;  e_off  = eo_off;
        hx_base = out; hx_off = hxo_off;
        hy_base = out; hy_off = hyo_off;
    }
}

// round 4
// speedup vs baseline: 1.7677x; 1.0125x over previous
#include <cuda_runtime.h>

// Problem constants (fixed: N=2048, B=2)
#define NN   2048
#define BB   2
#define EW   (NN + 1)            // 2049
#define HXH  (NN - 1)            // 2047
#define HXW  (NN)                // 2048
#define HYH  (NN)                // 2048
#define HYW  (NN - 1)            // 2047
#define EN   (EW * EW)
#define HXN  (HXH * HXW)
#define HYN  (HYH * HYW)
#define CFLF 0.35f

#define KF0 (-11.0f / 6.0f)
#define KF1 (3.0f)
#define KF2 (-1.5f)
#define KF3 (1.0f / 3.0f)
#define KB0 (-1.0f / 3.0f)
#define KB1 (1.5f)
#define KB2 (-3.0f)
#define KB3 (11.0f / 6.0f)

struct MCoef {
    float M00, M01, M02, M03, M11, M20, M21, M22, M23;
};

__device__ __forceinline__ MCoef make_M(const float* sb, const float* sd, const float* sg) {
    float beta = *sb, delta = *sd, gamma = *sg;
    MCoef m;
    m.M00 = -0.25f * beta + 0.1f * gamma;
    m.M01 =  0.25f * beta + delta - 0.5f - 0.1f * gamma;
    m.M02 =  0.25f * beta - 0.1f * gamma;
    m.M03 = -0.25f * beta + 0.1f * gamma;
    m.M11 = -2.0f * delta;
    m.M20 =  0.25f * beta - 0.1f * gamma;
    m.M21 = -0.25f * beta + delta + 0.5f + 0.1f * gamma;
    m.M22 = -0.25f * beta - 0.1f * gamma;
    m.M23 =  0.25f * beta + 0.1f * gamma;
    return m;
}

// ---------------------------------------------------------------------------
// Vectorized window load: out[t] = buf[idx+t], t=0..W-1, via aligned LDG.128.
// Skew (idx&3) is warp-uniform at all call sites. May read up to 3 floats
// before/after the window (stays inside the allocation at all call sites).
// ---------------------------------------------------------------------------
template<int W>
__device__ __forceinline__ void load_win(const float* __restrict__ buf, int idx,
                                         float* __restrict__ out)
{
    const int g0 = idx & ~3;
    const int k = idx & 3;
    const float4* p = reinterpret_cast<const float4*>(buf + g0);
#define LW_CASE(K)                                                         \
    case K: {                                                              \
        constexpr int NV = (W + (K) + 3) / 4;                              \
        float f[NV * 4];                                                   \
        _Pragma("unroll")                                                  \
        for (int t = 0; t < NV; t++)                                       \
            *reinterpret_cast<float4*>(f + 4 * t) = p[t];                  \
        _Pragma("unroll")                                                  \
        for (int t = 0; t < W; t++) out[t] = f[t + (K)];                   \
    } break;
    switch (k) {
        LW_CASE(0)
        LW_CASE(1)
        LW_CASE(2)
        LW_CASE(3)
    }
#undef LW_CASE
}

// ---------------------------------------------------------------------------
// Generic (boundary) amper point: returns s1 - s2 at (i,j).
// ---------------------------------------------------------------------------
__device__ float amper_point(const float* __restrict__ Hxb,
                             const float* __restrict__ Hyb,
                             int i, int j, const MCoef& m)
{
    float s1 = 0.0f, s2 = 0.0f;
    bool irow = (i >= 2 && i <= NN - 2);
    bool jcol = (j >= 2 && j <= NN - 2);

#define HYv(r, c) Hyb[(r) * HYW + (c)]
#define HXv(r, c) Hxb[(r) * HXW + (c)]
    if (irow && jcol) {
        s1 += m.M00 * HYv(i - 2, j - 2) + m.M20 * HYv(i - 2, j);
        s1 += m.M01 * HYv(i - 1, j - 2) + m.M11 * HYv(i - 1, j - 1) + m.M21 * HYv(i - 1, j);
        s1 += m.M02 * HYv(i,     j - 2) + m.M22 * HYv(i,     j);
        s1 += m.M03 * HYv(i + 1, j - 2) + m.M23 * HYv(i + 1, j);
        s2 += m.M00 * HXv(i - 2, j - 2) + m.M01 * HXv(i - 2, j - 1)
            + m.M02 * HXv(i - 2, j)     + m.M03 * HXv(i - 2, j + 1);
        s2 += m.M11 * HXv(i - 1, j - 1);
        s2 += m.M20 * HXv(i,     j - 2) + m.M21 * HXv(i,     j - 1)
            + m.M22 * HXv(i,     j)     + m.M23 * HXv(i,     j + 1);
    }
    if (i >= 1 && j <= NN - 5) {
        s1 += KF0 * HYv(i - 1, j)     + KF1 * HYv(i - 1, j + 1)
            + KF2 * HYv(i - 1, j + 2) + KF3 * HYv(i - 1, j + 3);
    }
    if (i <= NN - 1 && j >= 5) {
        s1 += KB0 * HYv(i, j - 5) + KB1 * HYv(i, j - 4)
            + KB2 * HYv(i, j - 3) + KB3 * HYv(i, j - 2);
    }
    if (irow && j >= 1 && j <= 2) {
        s1 += -HYv(i - 1, j - 1) + 3.0f * HYv(i - 1, j)
              - 3.0f * HYv(i - 1, j + 1) + HYv(i - 1, j + 2);
    }
    if (irow && j >= NN - 2 && j <= NN - 1) {
        s1 += HYv(i, j - 4) - 3.0f * HYv(i, j - 3)
            + 3.0f * HYv(i, j - 2) - HYv(i, j - 1);
    }
    if (j >= 1 && i <= NN - 5) {
        s2 += KF0 * HXv(i, j - 1)     + KF1 * HXv(i + 1, j - 1)
            + KF2 * HXv(i + 2, j - 1) + KF3 * HXv(i + 3, j - 1);
    }
    if (j <= NN - 1 && i >= 5) {
        s2 += KB0 * HXv(i - 5, j) + KB1 * HXv(i - 4, j)
            + KB2 * HXv(i - 3, j) + KB3 * HXv(i - 2, j);
    }
    if (jcol && i >= 1 && i <= 2) {
        s2 += -HXv(i - 1, j - 1) + 3.0f * HXv(i, j - 1)
              - 3.0f * HXv(i + 1, j - 1) + HXv(i + 2, j - 1);
    }
    if (jcol && i >= NN - 2 && i <= NN - 1) {
        s2 += HXv(i - 4, j) - 3.0f * HXv(i - 3, j)
            + 3.0f * HXv(i - 2, j) - HXv(i - 1, j);
    }
#undef HYv
#undef HXv
    return s1 - s2;
}

// ---------------------------------------------------------------------------
// Amper: 2 output rows x 4 cols per thread; shared Hy/Hx windows.
// ---------------------------------------------------------------------------
__global__ __launch_bounds__(128)
void k_amper(const float* __restrict__ e_base,  int e_off,
             const float* __restrict__ hx_base, int hx_off,
             const float* __restrict__ hy_base, int hy_off,
             float* __restrict__ out_base,      int eo_off,
             const float* __restrict__ sb,
             const float* __restrict__ sd,
             const float* __restrict__ sg)
{
    int t  = blockIdx.x * 32 + threadIdx.x;
    int i0 = (blockIdx.y * blockDim.y + threadIdx.y) * 2;
    if (i0 > NN) return;
    int b = blockIdx.z;

    const int erow0 = eo_off + b * EN + i0 * EW;   // row i0 output base
    const int s = erow0 & 3;                       // warp-uniform skew
    const int j = 4 * t - s;
    if (j + 3 < 0 || j > NN) return;

    MCoef m = make_M(sb, sd, sg);

    const int xb = hx_off + b * HXN;
    const int yb = hy_off + b * HYN;

    bool fast = (i0 >= 5) && (i0 <= NN - 6) && (j >= 5) && (j + 3 <= NN - 5);
    if (fast) {
        const float cM21KF0 = m.M21 + KF0;
        const float cM02KB3 = m.M02 + KB3;
        float s1a[4] = {0, 0, 0, 0}, s1b[4] = {0, 0, 0, 0};
        float s2a[4] = {0, 0, 0, 0}, s2b[4] = {0, 0, 0, 0};

        // ---- Hy union windows ----
        {
            float Y0[6];  load_win<6>(hy_base, yb + (i0 - 2) * HYW + (j - 2), Y0);
            #pragma unroll
            for (int q = 0; q < 4; q++)
                s1a[q] += m.M00 * Y0[q] + m.M20 * Y0[q + 2];
        }
        {
            float Y1[9];  load_win<9>(hy_base, yb + (i0 - 1) * HYW + (j - 2), Y1);
            #pragma unroll
            for (int q = 0; q < 4; q++) {
                s1a[q] += m.M01 * Y1[q] + m.M11 * Y1[q + 1] + cM21KF0 * Y1[q + 2]
                        + KF1 * Y1[q + 3] + KF2 * Y1[q + 4] + KF3 * Y1[q + 5];
                s1b[q] += m.M00 * Y1[q] + m.M20 * Y1[q + 2];
            }
        }
        {
            float Y2[12]; load_win<12>(hy_base, yb + i0 * HYW + (j - 5), Y2);
            #pragma unroll
            for (int q = 0; q < 4; q++) {
                s1a[q] += KB0 * Y2[q] + KB1 * Y2[q + 1] + KB2 * Y2[q + 2]
                        + cM02KB3 * Y2[q + 3] + m.M22 * Y2[q + 5];
                s1b[q] += m.M01 * Y2[q + 3] + m.M11 * Y2[q + 4] + cM21KF0 * Y2[q + 5]
                        + KF1 * Y2[q + 6] + KF2 * Y2[q + 7] + KF3 * Y2[q + 8];
            }
        }
        {
            float Y3[9];  load_win<9>(hy_base, yb + (i0 + 1) * HYW + (j - 5), Y3);
            #pragma unroll
            for (int q = 0; q < 4; q++) {
                s1a[q] += m.M03 * Y3[q + 3] + m.M23 * Y3[q + 5];
                s1b[q] += KB0 * Y3[q] + KB1 * Y3[q + 1] + KB2 * Y3[q + 2]
                        + cM02KB3 * Y3[q + 3] + m.M22 * Y3[q + 5];
            }
        }
        {
            float Y4[6];  load_win<6>(hy_base, yb + (i0 + 2) * HYW + (j - 2), Y4);
            #pragma unroll
            for (int q = 0; q < 4; q++)
                s1b[q] += m.M03 * Y4[q] + m.M23 * Y4[q + 2];
        }

        // ---- Hx union windows ----
        {
            float X0[4]; load_win<4>(hx_base, xb + (i0 - 5) * HXW + j, X0);
            float X1[4]; load_win<4>(hx_base, xb + (i0 - 4) * HXW + j, X1);
            float X2[4]; load_win<4>(hx_base, xb + (i0 - 3) * HXW + j, X2);
            #pragma unroll
            for (int q = 0; q < 4; q++) {
                s2a[q] += KB0 * X0[q] + KB1 * X1[q] + KB2 * X2[q];
                s2b[q] += KB0 * X1[q] + KB1 * X2[q];
            }
        }
        {
            float X3[7]; load_win<7>(hx_base, xb + (i0 - 2) * HXW + (j - 2), X3);
            #pragma unroll
            for (int q = 0; q < 4; q++) {
                s2a[q] += m.M00 * X3[q] + m.M01 * X3[q + 1]
                        + cM02KB3 * X3[q + 2] + m.M03 * X3[q + 3];
                s2b[q] += KB2 * X3[q + 2];
            }
        }
        {
            float X4[7]; load_win<7>(hx_base, xb + (i0 - 1) * HXW + (j - 2), X4);
            #pragma unroll
            for (int q = 0; q < 4; q++) {
                s2a[q] += m.M11 * X4[q + 1];
                s2b[q] += m.M00 * X4[q] + m.M01 * X4[q + 1]
                        + cM02KB3 * X4[q + 2] + m.M03 * X4[q + 3];
            }
        }
        {
            float X5[7]; load_win<7>(hx_base, xb + i0 * HXW + (j - 2), X5);
            #pragma unroll
            for (int q = 0; q < 4; q++) {
                s2a[q] += m.M20 * X5[q] + cM21KF0 * X5[q + 1]
                        + m.M22 * X5[q + 2] + m.M23 * X5[q + 3];
                s2b[q] += m.M11 * X5[q + 1];
            }
        }
        {
            float X6[7]; load_win<7>(hx_base, xb + (i0 + 1) * HXW + (j - 2), X6);
            #pragma unroll
            for (int q = 0; q < 4; q++) {
                s2a[q] += KF1 * X6[q + 1];
                s2b[q] += m.M20 * X6[q] + cM21KF0 * X6[q + 1]
                        + m.M22 * X6[q + 2] + m.M23 * X6[q + 3];
            }
        }
        {
            float X7[4]; load_win<4>(hx_base, xb + (i0 + 2) * HXW + (j - 1), X7);
            float X8[4]; load_win<4>(hx_base, xb + (i0 + 3) * HXW + (j - 1), X8);
            float X9[4]; load_win<4>(hx_base, xb + (i0 + 4) * HXW + (j - 1), X9);
            #pragma unroll
            for (int q = 0; q < 4; q++) {
                s2a[q] += KF2 * X7[q] + KF3 * X8[q];
                s2b[q] += KF1 * X7[q] + KF2 * X8[q] + KF3 * X9[q];
            }
        }

        // ---- E in + stores ----
        float E0[4], E1[4];
        load_win<4>(e_base, e_off + b * EN + i0 * EW + j, E0);
        load_win<4>(e_base, e_off + b * EN + (i0 + 1) * EW + j, E1);

        float4 w;
        w.x = E0[0] + CFLF * (s1a[0] - s2a[0]);
        w.y = E0[1] + CFLF * (s1a[1] - s2a[1]);
        w.z = E0[2] + CFLF * (s1a[2] - s2a[2]);
        w.w = E0[3] + CFLF * (s1a[3] - s2a[3]);
        *reinterpret_cast<float4*>(out_base + erow0 + j) = w;   // aligned

        float* w1 = out_base + erow0 + EW + j;                  // odd stride: scalar
        #pragma unroll
        for (int q = 0; q < 4; q++)
            w1[q] = E1[q] + CFLF * (s1b[q] - s2b[q]);
    } else {
        const float* Eb  = e_base + e_off + b * EN;
        const float* Hxb = hx_base + xb;
        const float* Hyb = hy_base + yb;
        float* Eob = out_base + eo_off + b * EN;
        #pragma unroll
        for (int r = 0; r < 2; r++) {
            int ii = i0 + r;
            if (ii > NN) continue;
            #pragma unroll
            for (int q = 0; q < 4; q++) {
                int jj = j + q;
                if (jj < 0 || jj > NN) continue;
                float d = amper_point(Hxb, Hyb, ii, jj, m);
                Eob[ii * EW + jj] = Eb[ii * EW + jj] + CFLF * d;
            }
        }
    }
}

// ---------------------------------------------------------------------------
// Generic faraday point helpers
// ---------------------------------------------------------------------------
__device__ float faraday_s3(const float* __restrict__ Eb, int i, int j, const MCoef& m)
{
#define Ev(r, c) Eb[(r) * EW + (c)]
    float s3 = 0.0f;
    if (j >= 1 && j <= NN - 2) {
        s3 += m.M00 * Ev(i,     j - 1) + m.M01 * Ev(i,     j)
            + m.M02 * Ev(i,     j + 1) + m.M03 * Ev(i,     j + 2);
        s3 += m.M11 * Ev(i + 1, j);
        s3 += m.M20 * Ev(i + 2, j - 1) + m.M21 * Ev(i + 2, j)
            + m.M22 * Ev(i + 2, j + 1) + m.M23 * Ev(i + 2, j + 2);
    }
    if (i <= NN - 4)
        s3 += -1.5f * Ev(i + 1, j) + 2.0f * Ev(i + 2, j) - 0.5f * Ev(i + 3, j);
    if (i >= 2)
        s3 += 0.5f * Ev(i - 1, j + 1) - 2.0f * Ev(i, j + 1) + 1.5f * Ev(i + 1, j + 1);
#undef Ev
    return s3;
}

__device__ float faraday_s4(const float* __restrict__ Eb, int i, int j, const MCoef& m)
{
#define Ev(r, c) Eb[(r) * EW + (c)]
    float s4 = 0.0f;
    if (i >= 1 && i <= NN - 2) {
        s4 += m.M00 * Ev(i - 1, j) + m.M20 * Ev(i - 1, j + 2);
        s4 += m.M01 * Ev(i,     j) + m.M11 * Ev(i, j + 1) + m.M21 * Ev(i, j + 2);
        s4 += m.M02 * Ev(i + 1, j) + m.M22 * Ev(i + 1, j + 2);
        s4 += m.M03 * Ev(i + 2, j) + m.M23 * Ev(i + 2, j + 2);
    }
    if (j <= NN - 4)
        s4 += -1.5f * Ev(i, j + 1) + 2.0f * Ev(i, j + 2) - 0.5f * Ev(i, j + 3);
    if (j >= 2)
        s4 += 0.5f * Ev(i + 1, j - 1) - 2.0f * Ev(i + 1, j) + 1.5f * Ev(i + 1, j + 1);
#undef Ev
    return s4;
}

// ---------------------------------------------------------------------------
// Fused faraday: 2 output rows x 4 cols per thread; shared E windows.
// ---------------------------------------------------------------------------
__global__ __launch_bounds__(128)
void k_faraday(const float* __restrict__ e_base,  int e_off,
               const float* __restrict__ hx_base, int hx_off,
               const float* __restrict__ hy_base, int hy_off,
               float* __restrict__ out_base,      int hxo_off, int hyo_off,
               const float* __restrict__ sb,
               const float* __restrict__ sd,
               const float* __restrict__ sg)
{
    int t  = blockIdx.x * 32 + threadIdx.x;
    int i0 = (blockIdx.y * blockDim.y + threadIdx.y) * 2;
    if (i0 >= NN) return;
    int b = blockIdx.z;

    const int sF = hxo_off & 3;           // launch-uniform Hx-output skew
    const int j = 4 * t - sF;
    if (j + 3 < 0 || j >= NN) return;

    MCoef m = make_M(sb, sd, sg);

    const int eb = e_off + b * EN;
    const int xb = hx_off + b * HXN;
    const int yb = hy_off + b * HYN;

    bool fast = (i0 >= 2) && (i0 <= NN - 5) && (j >= 2) && (j + 3 <= NN - 4);
    if (fast) {
        const float cA = m.M02 - 2.0f;
        const float cB = m.M11 - 1.5f;
        const float cC = m.M21 + 2.0f;
        float s3a[4] = {0, 0, 0, 0}, s3b[4] = {0, 0, 0, 0};
        float s4a[4] = {0, 0, 0, 0}, s4b[4] = {0, 0, 0, 0};

        {
            float W0[6]; load_win<6>(e_base, eb + (i0 - 1) * EW + j, W0);
            #pragma unroll
            for (int q = 0; q < 4; q++) {
                s3a[q] += 0.5f * W0[q + 1];
                s4a[q] += m.M00 * W0[q] + m.M20 * W0[q + 2];
            }
        }
        {
            float W1[8]; load_win<8>(e_base, eb + i0 * EW + (j - 1), W1);
            #pragma unroll
            for (int q = 0; q < 4; q++) {
                s3a[q] += m.M00 * W1[q] + m.M01 * W1[q + 1] + cA * W1[q + 2] + m.M03 * W1[q + 3];
                s4a[q] += m.M01 * W1[q + 1] + cB * W1[q + 2] + cC * W1[q + 3] - 0.5f * W1[q + 4];
                s3b[q] += 0.5f * W1[q + 2];
                s4b[q] += m.M00 * W1[q + 1] + m.M20 * W1[q + 3];
            }
        }
        {
            float W2[8]; load_win<8>(e_base, eb + (i0 + 1) * EW + (j - 1), W2);
            #pragma unroll
            for (int q = 0; q < 4; q++) {
                s3a[q] += cB * W2[q + 1] + 1.5f * W2[q + 2];
                s4a[q] += 0.5f * W2[q] + cA * W2[q + 1] + 1.5f * W2[q + 2] + m.M22 * W2[q + 3];
                s3b[q] += m.M00 * W2[q] + m.M01 * W2[q + 1] + cA * W2[q + 2] + m.M03 * W2[q + 3];
                s4b[q] += m.M01 * W2[q + 1] + cB * W2[q + 2] + cC * W2[q + 3] - 0.5f * W2[q + 4];
            }
        }
        {
            float W3[7]; load_win<7>(e_base, eb + (i0 + 2) * EW + (j - 1), W3);
            #pragma unroll
            for (int q = 0; q < 4; q++) {
                s3a[q] += m.M20 * W3[q] + cC * W3[q + 1] + m.M22 * W3[q + 2] + m.M23 * W3[q + 3];
                s4a[q] += m.M03 * W3[q + 1] + m.M23 * W3[q + 3];
                s3b[q] += cB * W3[q + 1] + 1.5f * W3[q + 2];
                s4b[q] += 0.5f * W3[q] + cA * W3[q + 1] + 1.5f * W3[q + 2] + m.M22 * W3[q + 3];
            }
        }
        {
            float W4[7]; load_win<7>(e_base, eb + (i0 + 3) * EW + (j - 1), W4);
            #pragma unroll
            for (int q = 0; q < 4; q++) {
                s3a[q] += -0.5f * W4[q + 1];
                s3b[q] += m.M20 * W4[q] + cC * W4[q + 1] + m.M22 * W4[q + 2] + m.M23 * W4[q + 3];
                s4b[q] += m.M03 * W4[q + 1] + m.M23 * W4[q + 3];
            }
        }
        {
            float W5[4]; load_win<4>(e_base, eb + (i0 + 4) * EW + j, W5);
            #pragma unroll
            for (int q = 0; q < 4; q++)
                s3b[q] += -0.5f * W5[q];
        }

        float hx0[4], hx1[4], hy0[4], hy1[4];
        load_win<4>(hx_base, xb + i0 * HXW + j, hx0);
        load_win<4>(hx_base, xb + (i0 + 1) * HXW + j, hx1);
        load_win<4>(hy_base, yb + i0 * HYW + j, hy0);
        load_win<4>(hy_base, yb + (i0 + 1) * HYW + j, hy1);

        // Hx stores: aligned STG.128 both rows (HXW mult of 4)
        float4 wx;
        wx.x = hx0[0] - CFLF * s3a[0];
        wx.y = hx0[1] - CFLF * s3a[1];
        wx.z = hx0[2] - CFLF * s3a[2];
        wx.w = hx0[3] - CFLF * s3a[3];
        *reinterpret_cast<float4*>(out_base + hxo_off + b * HXN + i0 * HXW + j) = wx;
        wx.x = hx1[0] - CFLF * s3b[0];
        wx.y = hx1[1] - CFLF * s3b[1];
        wx.z = hx1[2] - CFLF * s3b[2];
        wx.w = hx1[3] - CFLF * s3b[3];
        *reinterpret_cast<float4*>(out_base + hxo_off + b * HXN + (i0 + 1) * HXW + j) = wx;

        // Hy stores: odd stride, scalar
        float* hyw0 = out_base + hyo_off + b * HYN + i0 * HYW + j;
        float* hyw1 = hyw0 + HYW;
        #pragma unroll
        for (int q = 0; q < 4; q++) {
            hyw0[q] = hy0[q] + CFLF * s4a[q];
            hyw1[q] = hy1[q] + CFLF * s4b[q];
        }
    } else {
        const float* Eb  = e_base + eb;
        const float* Hxb = hx_base + xb;
        const float* Hyb = hy_base + yb;
        float* Hxob = out_base + hxo_off + b * HXN;
        float* Hyob = out_base + hyo_off + b * HYN;
        #pragma unroll
        for (int r = 0; r < 2; r++) {
            int ii = i0 + r;
            if (ii >= NN) continue;
            #pragma unroll
            for (int q = 0; q < 4; q++) {
                int jj = j + q;
                if (jj < 0 || jj >= NN) continue;
                if (ii < HXH && jj < HXW) {
                    float s3 = faraday_s3(Eb, ii, jj, m);
                    Hxob[ii * HXW + jj] = Hxb[ii * HXW + jj] - CFLF * s3;
                }
                if (ii < HYH && jj < HYW) {
                    float s4 = faraday_s4(Eb, ii, jj, m);
                    Hyob[ii * HYW + jj] = Hyb[ii * HYW + jj] + CFLF * s4;
                }
            }
        }
    }
}

// ---------------------------------------------------------------------------
extern "C" void kernel_launch(void* const* d_in, const int* in_sizes, int n_in,
                              void* d_out, int out_size)
{
    const float* sb = (const float*)d_in[3];
    const float* sd = (const float*)d_in[4];
    const float* sg = (const float*)d_in[5];
    float* out = (float*)d_out;

    const float* e_base  = (const float*)d_in[0]; int e_off  = 0;
    const float* hx_base = (const float*)d_in[1]; int hx_off = 0;
    const float* hy_base = (const float*)d_in[2]; int hy_off = 0;

    const int STEP = BB * (EN + HXN + HYN);

    dim3 blk(32, 4, 1);
    // j: t in [0, 512] -> 513 strips -> 17 x-blocks. rows: 2-row strips.
    dim3 gE(17, (1025 + 3) / 4, BB);   // 1025 row-strips cover 2049 rows
    dim3 gF(17, 1024 / 4, BB);         // 1024 row-strips cover 2048 rows

    for (int k = 0; k < 3; k++) {
        int eo_off  = k * STEP;
        int hxo_off = eo_off + BB * EN;
        int hyo_off = hxo_off + BB * HXN;

        k_amper<<<gE, blk>>>(e_base, e_off, hx_base, hx_off, hy_base, hy_off,
                             out, eo_off, sb, sd, sg);
        k_faraday<<<gF, blk>>>(out, eo_off, hx_base, hx_off, hy_base, hy_off,
                               out, hxo_off, hyo_off, sb, sd, sg);

        e_base = out;  e_off  = eo_off;
        hx_base = out; hx_off = hxo_off;
        hy_base = out; hy_off = hyo_off;
    }
}

// round 5
// speedup vs baseline: 2.1192x; 1.1989x over previous
#include <cuda_runtime.h>

// Problem constants (fixed: N=2048, B=2)
#define NN   2048
#define BB   2
#define EW   (NN + 1)            // 2049  (== 1 mod 4)
#define HXH  (NN - 1)            // 2047
#define HXW  (NN)                // 2048  (== 0 mod 4)
#define HYH  (NN)                // 2048
#define HYW  (NN - 1)            // 2047  (== 3 mod 4)
#define EN   (EW * EW)
#define HXN  (HXH * HXW)
#define HYN  (HYH * HYW)
#define CFLF 0.35f

#define KF0 (-11.0f / 6.0f)
#define KF1 (3.0f)
#define KF2 (-1.5f)
#define KF3 (1.0f / 3.0f)
#define KB0 (-1.0f / 3.0f)
#define KB1 (1.5f)
#define KB2 (-3.0f)
#define KB3 (11.0f / 6.0f)

struct MCoef {
    float M00, M01, M02, M03, M11, M20, M21, M22, M23;
};

__device__ __forceinline__ MCoef make_M(const float* sb, const float* sd, const float* sg) {
    float beta = *sb, delta = *sd, gamma = *sg;
    MCoef m;
    m.M00 = -0.25f * beta + 0.1f * gamma;
    m.M01 =  0.25f * beta + delta - 0.5f - 0.1f * gamma;
    m.M02 =  0.25f * beta - 0.1f * gamma;
    m.M03 = -0.25f * beta + 0.1f * gamma;
    m.M11 = -2.0f * delta;
    m.M20 =  0.25f * beta - 0.1f * gamma;
    m.M21 = -0.25f * beta + delta + 0.5f + 0.1f * gamma;
    m.M22 = -0.25f * beta - 0.1f * gamma;
    m.M23 =  0.25f * beta + 0.1f * gamma;
    return m;
}

// ---------------------------------------------------------------------------
// Compile-time-skew window load: out[t] = buf[idx+t], requires (idx&3)==K.
// Aligned LDG.128, straight-line (no branches). May touch up to 3 floats
// before/after the window — interior-only call sites keep this in-bounds.
// ---------------------------------------------------------------------------
template<int W, int K>
__device__ __forceinline__ void load_win_k(const float* __restrict__ buf, int idx,
                                           float* __restrict__ out)
{
    constexpr int NV = (W + K + 3) / 4;
    const float4* p = reinterpret_cast<const float4*>(buf + (idx - K));
    float f[NV * 4];
    #pragma unroll
    for (int t = 0; t < NV; t++)
        *reinterpret_cast<float4*>(f + 4 * t) = p[t];
    #pragma unroll
    for (int t = 0; t < W; t++) out[t] = f[t + K];
}

// ---------------------------------------------------------------------------
// Generic (boundary) amper point: returns s1 - s2 at (i,j).
// ---------------------------------------------------------------------------
__device__ float amper_point(const float* __restrict__ Hxb,
                             const float* __restrict__ Hyb,
                             int i, int j, const MCoef& m)
{
    float s1 = 0.0f, s2 = 0.0f;
    bool irow = (i >= 2 && i <= NN - 2);
    bool jcol = (j >= 2 && j <= NN - 2);

#define HYv(r, c) Hyb[(r) * HYW + (c)]
#define HXv(r, c) Hxb[(r) * HXW + (c)]
    if (irow && jcol) {
        s1 += m.M00 * HYv(i - 2, j - 2) + m.M20 * HYv(i - 2, j);
        s1 += m.M01 * HYv(i - 1, j - 2) + m.M11 * HYv(i - 1, j - 1) + m.M21 * HYv(i - 1, j);
        s1 += m.M02 * HYv(i,     j - 2) + m.M22 * HYv(i,     j);
        s1 += m.M03 * HYv(i + 1, j - 2) + m.M23 * HYv(i + 1, j);
        s2 += m.M00 * HXv(i - 2, j - 2) + m.M01 * HXv(i - 2, j - 1)
            + m.M02 * HXv(i - 2, j)     + m.M03 * HXv(i - 2, j + 1);
        s2 += m.M11 * HXv(i - 1, j - 1);
        s2 += m.M20 * HXv(i,     j - 2) + m.M21 * HXv(i,     j - 1)
            + m.M22 * HXv(i,     j)     + m.M23 * HXv(i,     j + 1);
    }
    if (i >= 1 && j <= NN - 5) {
        s1 += KF0 * HYv(i - 1, j)     + KF1 * HYv(i - 1, j + 1)
            + KF2 * HYv(i - 1, j + 2) + KF3 * HYv(i - 1, j + 3);
    }
    if (i <= NN - 1 && j >= 5) {
        s1 += KB0 * HYv(i, j - 5) + KB1 * HYv(i, j - 4)
            + KB2 * HYv(i, j - 3) + KB3 * HYv(i, j - 2);
    }
    if (irow && j >= 1 && j <= 2) {
        s1 += -HYv(i - 1, j - 1) + 3.0f * HYv(i - 1, j)
              - 3.0f * HYv(i - 1, j + 1) + HYv(i - 1, j + 2);
    }
    if (irow && j >= NN - 2 && j <= NN - 1) {
        s1 += HYv(i, j - 4) - 3.0f * HYv(i, j - 3)
            + 3.0f * HYv(i, j - 2) - HYv(i, j - 1);
    }
    if (j >= 1 && i <= NN - 5) {
        s2 += KF0 * HXv(i, j - 1)     + KF1 * HXv(i + 1, j - 1)
            + KF2 * HXv(i + 2, j - 1) + KF3 * HXv(i + 3, j - 1);
    }
    if (j <= NN - 1 && i >= 5) {
        s2 += KB0 * HXv(i - 5, j) + KB1 * HXv(i - 4, j)
            + KB2 * HXv(i - 3, j) + KB3 * HXv(i - 2, j);
    }
    if (jcol && i >= 1 && i <= 2) {
        s2 += -HXv(i - 1, j - 1) + 3.0f * HXv(i, j - 1)
              - 3.0f * HXv(i + 1, j - 1) + HXv(i + 2, j - 1);
    }
    if (jcol && i >= NN - 2 && i <= NN - 1) {
        s2 += HXv(i - 4, j) - 3.0f * HXv(i - 3, j)
            + 3.0f * HXv(i - 2, j) - HXv(i - 1, j);
    }
#undef HYv
#undef HXv
    return s1 - s2;
}

// ---------------------------------------------------------------------------
// Amper Hy section (rows i0-2 .. i0+2). KY = skew of base window.
// base = yb + (i0-2)*HYW + (j-2). Row stride HYW == 3 (mod 4).
// ---------------------------------------------------------------------------
template<int KY>
__device__ __forceinline__ void amper_hy_sec(const float* __restrict__ hy, int base,
                                             const MCoef& m, float cM21KF0, float cM02KB3,
                                             float* __restrict__ s1a, float* __restrict__ s1b)
{
    float Y0[6], Y1[9], Y2[12], Y3[9], Y4[6];
    load_win_k<6,  KY          >(hy, base, Y0);
    load_win_k<9,  (KY + 3) & 3>(hy, base + HYW, Y1);
    load_win_k<12, (KY + 3) & 3>(hy, base + 2 * HYW - 3, Y2);
    load_win_k<9,  (KY + 2) & 3>(hy, base + 3 * HYW - 3, Y3);
    load_win_k<6,  KY          >(hy, base + 4 * HYW, Y4);

    #pragma unroll
    for (int q = 0; q < 4; q++) {
        s1a[q] += m.M00 * Y0[q] + m.M20 * Y0[q + 2];
        s1a[q] += m.M01 * Y1[q] + m.M11 * Y1[q + 1] + cM21KF0 * Y1[q + 2]
                + KF1 * Y1[q + 3] + KF2 * Y1[q + 4] + KF3 * Y1[q + 5];
        s1b[q] += m.M00 * Y1[q] + m.M20 * Y1[q + 2];
        s1a[q] += KB0 * Y2[q] + KB1 * Y2[q + 1] + KB2 * Y2[q + 2]
                + cM02KB3 * Y2[q + 3] + m.M22 * Y2[q + 5];
        s1b[q] += m.M01 * Y2[q + 3] + m.M11 * Y2[q + 4] + cM21KF0 * Y2[q + 5]
                + KF1 * Y2[q + 6] + KF2 * Y2[q + 7] + KF3 * Y2[q + 8];
        s1a[q] += m.M03 * Y3[q + 3] + m.M23 * Y3[q + 5];
        s1b[q] += KB0 * Y3[q] + KB1 * Y3[q + 1] + KB2 * Y3[q + 2]
                + cM02KB3 * Y3[q + 3] + m.M22 * Y3[q + 5];
        s1b[q] += m.M03 * Y4[q] + m.M23 * Y4[q + 2];
    }
}

// ---------------------------------------------------------------------------
// Amper Hx section (rows i0-5 .. i0+4). KX = skew of base window.
// base = xb + (i0-5)*HXW + j. Row stride HXW == 0 (mod 4).
// ---------------------------------------------------------------------------
template<int KX>
__device__ __forceinline__ void amper_hx_sec(const float* __restrict__ hx, int base,
                                             const MCoef& m, float cM21KF0, float cM02KB3,
                                             float* __restrict__ s2a, float* __restrict__ s2b)
{
    float X0[4], X1[4], X2[4], X3[7], X4[7], X5[7], X6[7], X7[4], X8[4], X9[4];
    load_win_k<4, KX          >(hx, base, X0);
    load_win_k<4, KX          >(hx, base + HXW, X1);
    load_win_k<4, KX          >(hx, base + 2 * HXW, X2);
    load_win_k<7, (KX + 2) & 3>(hx, base + 3 * HXW - 2, X3);
    load_win_k<7, (KX + 2) & 3>(hx, base + 4 * HXW - 2, X4);
    load_win_k<7, (KX + 2) & 3>(hx, base + 5 * HXW - 2, X5);
    load_win_k<7, (KX + 2) & 3>(hx, base + 6 * HXW - 2, X6);
    load_win_k<4, (KX + 3) & 3>(hx, base + 7 * HXW - 1, X7);
    load_win_k<4, (KX + 3) & 3>(hx, base + 8 * HXW - 1, X8);
    load_win_k<4, (KX + 3) & 3>(hx, base + 9 * HXW - 1, X9);

    #pragma unroll
    for (int q = 0; q < 4; q++) {
        s2a[q] += KB0 * X0[q] + KB1 * X1[q] + KB2 * X2[q];
        s2b[q] += KB0 * X1[q] + KB1 * X2[q];
        s2a[q] += m.M00 * X3[q] + m.M01 * X3[q + 1] + cM02KB3 * X3[q + 2] + m.M03 * X3[q + 3];
        s2b[q] += KB2 * X3[q + 2];
        s2a[q] += m.M11 * X4[q + 1];
        s2b[q] += m.M00 * X4[q] + m.M01 * X4[q + 1] + cM02KB3 * X4[q + 2] + m.M03 * X4[q + 3];
        s2a[q] += m.M20 * X5[q] + cM21KF0 * X5[q + 1] + m.M22 * X5[q + 2] + m.M23 * X5[q + 3];
        s2b[q] += m.M11 * X5[q + 1];
        s2a[q] += KF1 * X6[q + 1];
        s2b[q] += m.M20 * X6[q] + cM21KF0 * X6[q + 1] + m.M22 * X6[q + 2] + m.M23 * X6[q + 3];
        s2a[q] += KF2 * X7[q] + KF3 * X8[q];
        s2b[q] += KF1 * X7[q] + KF2 * X8[q] + KF3 * X9[q];
    }
}

// ---------------------------------------------------------------------------
// Amper: 2 output rows x 4 cols per thread.
// ---------------------------------------------------------------------------
__global__ __launch_bounds__(128)
void k_amper(const float* __restrict__ e_base,  int e_off,
             const float* __restrict__ hx_base, int hx_off,
             const float* __restrict__ hy_base, int hy_off,
             float* __restrict__ out_base,      int eo_off,
             const float* __restrict__ sb,
             const float* __restrict__ sd,
             const float* __restrict__ sg)
{
    int t  = blockIdx.x * 32 + threadIdx.x;
    int i0 = (blockIdx.y * blockDim.y + threadIdx.y) * 2;
    if (i0 > NN) return;
    int b = blockIdx.z;

    const int erow0 = eo_off + b * EN + i0 * EW;
    const int s = erow0 & 3;
    const int j = 4 * t - s;
    if (j + 3 < 0 || j > NN) return;

    MCoef m = make_M(sb, sd, sg);

    const int xb = hx_off + b * HXN;
    const int yb = hy_off + b * HYN;

    bool fast = (i0 >= 5) && (i0 <= NN - 6) && (j >= 5) && (j + 3 <= NN - 5);
    if (fast) {
        const float cM21KF0 = m.M21 + KF0;
        const float cM02KB3 = m.M02 + KB3;
        float s1a[4] = {0, 0, 0, 0}, s1b[4] = {0, 0, 0, 0};
        float s2a[4] = {0, 0, 0, 0}, s2b[4] = {0, 0, 0, 0};

        // E in (skew known per launch; 1 small switch covers both rows; EW == 1 mod 4)
        float E0[4], E1[4];
        const int eidx = e_off + b * EN + i0 * EW + j;
        switch (eidx & 3) {
            case 0: load_win_k<4, 0>(e_base, eidx, E0); load_win_k<4, 1>(e_base, eidx + EW, E1); break;
            case 1: load_win_k<4, 1>(e_base, eidx, E0); load_win_k<4, 2>(e_base, eidx + EW, E1); break;
            case 2: load_win_k<4, 2>(e_base, eidx, E0); load_win_k<4, 3>(e_base, eidx + EW, E1); break;
            case 3: load_win_k<4, 3>(e_base, eidx, E0); load_win_k<4, 0>(e_base, eidx + EW, E1); break;
        }

        // Hy section: one switch, straight-line loads inside
        const int ybase = yb + (i0 - 2) * HYW + (j - 2);
        switch (ybase & 3) {
            case 0: amper_hy_sec<0>(hy_base, ybase, m, cM21KF0, cM02KB3, s1a, s1b); break;
            case 1: amper_hy_sec<1>(hy_base, ybase, m, cM21KF0, cM02KB3, s1a, s1b); break;
            case 2: amper_hy_sec<2>(hy_base, ybase, m, cM21KF0, cM02KB3, s1a, s1b); break;
            case 3: amper_hy_sec<3>(hy_base, ybase, m, cM21KF0, cM02KB3, s1a, s1b); break;
        }

        // Hx section: one switch
        const int xbase = xb + (i0 - 5) * HXW + j;
        switch (xbase & 3) {
            case 0: amper_hx_sec<0>(hx_base, xbase, m, cM21KF0, cM02KB3, s2a, s2b); break;
            case 1: amper_hx_sec<1>(hx_base, xbase, m, cM21KF0, cM02KB3, s2a, s2b); break;
            case 2: amper_hx_sec<2>(hx_base, xbase, m, cM21KF0, cM02KB3, s2a, s2b); break;
            case 3: amper_hx_sec<3>(hx_base, xbase, m, cM21KF0, cM02KB3, s2a, s2b); break;
        }

        float4 w;
        w.x = E0[0] + CFLF * (s1a[0] - s2a[0]);
        w.y = E0[1] + CFLF * (s1a[1] - s2a[1]);
        w.z = E0[2] + CFLF * (s1a[2] - s2a[2]);
        w.w = E0[3] + CFLF * (s1a[3] - s2a[3]);
        *reinterpret_cast<float4*>(out_base + erow0 + j) = w;   // aligned

        float* w1 = out_base + erow0 + EW + j;                  // odd stride: scalar
        #pragma unroll
        for (int q = 0; q < 4; q++)
            w1[q] = E1[q] + CFLF * (s1b[q] - s2b[q]);
    } else {
        const float* Eb  = e_base + e_off + b * EN;
        const float* Hxb = hx_base + xb;
        const float* Hyb = hy_base + yb;
        float* Eob = out_base + eo_off + b * EN;
        #pragma unroll
        for (int r = 0; r < 2; r++) {
            int ii = i0 + r;
            if (ii > NN) continue;
            #pragma unroll
            for (int q = 0; q < 4; q++) {
                int jj = j + q;
                if (jj < 0 || jj > NN) continue;
                float d = amper_point(Hxb, Hyb, ii, jj, m);
                Eob[ii * EW + jj] = Eb[ii * EW + jj] + CFLF * d;
            }
        }
    }
}

// ---------------------------------------------------------------------------
// Generic faraday point helpers
// ---------------------------------------------------------------------------
__device__ float faraday_s3(const float* __restrict__ Eb, int i, int j, const MCoef& m)
{
#define Ev(r, c) Eb[(r) * EW + (c)]
    float s3 = 0.0f;
    if (j >= 1 && j <= NN - 2) {
        s3 += m.M00 * Ev(i,     j - 1) + m.M01 * Ev(i,     j)
            + m.M02 * Ev(i,     j + 1) + m.M03 * Ev(i,     j + 2);
        s3 += m.M11 * Ev(i + 1, j);
        s3 += m.M20 * Ev(i + 2, j - 1) + m.M21 * Ev(i + 2, j)
            + m.M22 * Ev(i + 2, j + 1) + m.M23 * Ev(i + 2, j + 2);
    }
    if (i <= NN - 4)
        s3 += -1.5f * Ev(i + 1, j) + 2.0f * Ev(i + 2, j) - 0.5f * Ev(i + 3, j);
    if (i >= 2)
        s3 += 0.5f * Ev(i - 1, j + 1) - 2.0f * Ev(i, j + 1) + 1.5f * Ev(i + 1, j + 1);
#undef Ev
    return s3;
}

__device__ float faraday_s4(const float* __restrict__ Eb, int i, int j, const MCoef& m)
{
#define Ev(r, c) Eb[(r) * EW + (c)]
    float s4 = 0.0f;
    if (i >= 1 && i <= NN - 2) {
        s4 += m.M00 * Ev(i - 1, j) + m.M20 * Ev(i - 1, j + 2);
        s4 += m.M01 * Ev(i,     j) + m.M11 * Ev(i, j + 1) + m.M21 * Ev(i, j + 2);
        s4 += m.M02 * Ev(i + 1, j) + m.M22 * Ev(i + 1, j + 2);
        s4 += m.M03 * Ev(i + 2, j) + m.M23 * Ev(i + 2, j + 2);
    }
    if (j <= NN - 4)
        s4 += -1.5f * Ev(i, j + 1) + 2.0f * Ev(i, j + 2) - 0.5f * Ev(i, j + 3);
    if (j >= 2)
        s4 += 0.5f * Ev(i + 1, j - 1) - 2.0f * Ev(i + 1, j) + 1.5f * Ev(i + 1, j + 1);
#undef Ev
    return s4;
}

// ---------------------------------------------------------------------------
// Faraday E section (rows i0-1 .. i0+4). KE = skew of base window.
// base = eb + (i0-1)*EW + j. Row stride EW == 1 (mod 4).
// ---------------------------------------------------------------------------
template<int KE>
__device__ __forceinline__ void faraday_e_sec(const float* __restrict__ e, int base,
                                              const MCoef& m, float cA, float cB, float cC,
                                              float* __restrict__ s3a, float* __restrict__ s3b,
                                              float* __restrict__ s4a, float* __restrict__ s4b)
{
    float W0[6], W1[8], W2[8], W3[7], W4[7], W5[4];
    load_win_k<6, KE          >(e, base, W0);
    load_win_k<8, KE          >(e, base + EW - 1, W1);
    load_win_k<8, (KE + 1) & 3>(e, base + 2 * EW - 1, W2);
    load_win_k<7, (KE + 2) & 3>(e, base + 3 * EW - 1, W3);
    load_win_k<7, (KE + 3) & 3>(e, base + 4 * EW - 1, W4);
    load_win_k<4, (KE + 1) & 3>(e, base + 5 * EW, W5);

    #pragma unroll
    for (int q = 0; q < 4; q++) {
        s3a[q] += 0.5f * W0[q + 1];
        s4a[q] += m.M00 * W0[q] + m.M20 * W0[q + 2];
        s3a[q] += m.M00 * W1[q] + m.M01 * W1[q + 1] + cA * W1[q + 2] + m.M03 * W1[q + 3];
        s4a[q] += m.M01 * W1[q + 1] + cB * W1[q + 2] + cC * W1[q + 3] - 0.5f * W1[q + 4];
        s3b[q] += 0.5f * W1[q + 2];
        s4b[q] += m.M00 * W1[q + 1] + m.M20 * W1[q + 3];
        s3a[q] += cB * W2[q + 1] + 1.5f * W2[q + 2];
        s4a[q] += 0.5f * W2[q] + cA * W2[q + 1] + 1.5f * W2[q + 2] + m.M22 * W2[q + 3];
        s3b[q] += m.M00 * W2[q] + m.M01 * W2[q + 1] + cA * W2[q + 2] + m.M03 * W2[q + 3];
        s4b[q] += m.M01 * W2[q + 1] + cB * W2[q + 2] + cC * W2[q + 3] - 0.5f * W2[q + 4];
        s3a[q] += m.M20 * W3[q] + cC * W3[q + 1] + m.M22 * W3[q + 2] + m.M23 * W3[q + 3];
        s4a[q] += m.M03 * W3[q + 1] + m.M23 * W3[q + 3];
        s3b[q] += cB * W3[q + 1] + 1.5f * W3[q + 2];
        s4b[q] += 0.5f * W3[q] + cA * W3[q + 1] + 1.5f * W3[q + 2] + m.M22 * W3[q + 3];
        s3a[q] += -0.5f * W4[q + 1];
        s3b[q] += m.M20 * W4[q] + cC * W4[q + 1] + m.M22 * W4[q + 2] + m.M23 * W4[q + 3];
        s4b[q] += m.M03 * W4[q + 1] + m.M23 * W4[q + 3];
        s3b[q] += -0.5f * W5[q];
    }
}

// ---------------------------------------------------------------------------
// Fused faraday: 2 output rows x 4 cols per thread.
// ---------------------------------------------------------------------------
__global__ __launch_bounds__(128)
void k_faraday(const float* __restrict__ e_base,  int e_off,
               const float* __restrict__ hx_base, int hx_off,
               const float* __restrict__ hy_base, int hy_off,
               float* __restrict__ out_base,      int hxo_off, int hyo_off,
               const float* __restrict__ sb,
               const float* __restrict__ sd,
               const float* __restrict__ sg)
{
    int t  = blockIdx.x * 32 + threadIdx.x;
    int i0 = (blockIdx.y * blockDim.y + threadIdx.y) * 2;
    if (i0 >= NN) return;
    int b = blockIdx.z;

    const int sF = hxo_off & 3;
    const int j = 4 * t - sF;
    if (j + 3 < 0 || j >= NN) return;

    MCoef m = make_M(sb, sd, sg);

    const int eb = e_off + b * EN;
    const int xb = hx_off + b * HXN;
    const int yb = hy_off + b * HYN;

    bool fast = (i0 >= 2) && (i0 <= NN - 5) && (j >= 2) && (j + 3 <= NN - 4);
    if (fast) {
        const float cA = m.M02 - 2.0f;
        const float cB = m.M11 - 1.5f;
        const float cC = m.M21 + 2.0f;
        float s3a[4] = {0, 0, 0, 0}, s3b[4] = {0, 0, 0, 0};
        float s4a[4] = {0, 0, 0, 0}, s4b[4] = {0, 0, 0, 0};

        // Issue H loads first (independent of E stencil) for overlap.
        float hx0[4], hx1[4], hy0[4], hy1[4];
        const int hxidx = xb + i0 * HXW + j;          // HXW == 0 mod 4: same skew both rows
        switch (hxidx & 3) {
            case 0: load_win_k<4, 0>(hx_base, hxidx, hx0); load_win_k<4, 0>(hx_base, hxidx + HXW, hx1); break;
            case 1: load_win_k<4, 1>(hx_base, hxidx, hx0); load_win_k<4, 1>(hx_base, hxidx + HXW, hx1); break;
            case 2: load_win_k<4, 2>(hx_base, hxidx, hx0); load_win_k<4, 2>(hx_base, hxidx + HXW, hx1); break;
            case 3: load_win_k<4, 3>(hx_base, hxidx, hx0); load_win_k<4, 3>(hx_base, hxidx + HXW, hx1); break;
        }
        const int hyidx = yb + i0 * HYW + j;          // HYW == 3 mod 4: row 1 skew +3
        switch (hyidx & 3) {
            case 0: load_win_k<4, 0>(hy_base, hyidx, hy0); load_win_k<4, 3>(hy_base, hyidx + HYW, hy1); break;
            case 1: load_win_k<4, 1>(hy_base, hyidx, hy0); load_win_k<4, 0>(hy_base, hyidx + HYW, hy1); break;
            case 2: load_win_k<4, 2>(hy_base, hyidx, hy0); load_win_k<4, 1>(hy_base, hyidx + HYW, hy1); break;
            case 3: load_win_k<4, 3>(hy_base, hyidx, hy0); load_win_k<4, 2>(hy_base, hyidx + HYW, hy1); break;
        }

        // E section: one switch, 13 straight-line LDG.128 inside.
        const int ebase = eb + (i0 - 1) * EW + j;
        switch (ebase & 3) {
            case 0: faraday_e_sec<0>(e_base, ebase, m, cA, cB, cC, s3a, s3b, s4a, s4b); break;
            case 1: faraday_e_sec<1>(e_base, ebase, m, cA, cB, cC, s3a, s3b, s4a, s4b); break;
            case 2: faraday_e_sec<2>(e_base, ebase, m, cA, cB, cC, s3a, s3b, s4a, s4b); break;
            case 3: faraday_e_sec<3>(e_base, ebase, m, cA, cB, cC, s3a, s3b, s4a, s4b); break;
        }

        // Hx stores: aligned STG.128 both rows
        float4 wx;
        wx.x = hx0[0] - CFLF * s3a[0];
        wx.y = hx0[1] - CFLF * s3a[1];
        wx.z = hx0[2] - CFLF * s3a[2];
        wx.w = hx0[3] - CFLF * s3a[3];
        *reinterpret_cast<float4*>(out_base + hxo_off + b * HXN + i0 * HXW + j) = wx;
        wx.x = hx1[0] - CFLF * s3b[0];
        wx.y = hx1[1] - CFLF * s3b[1];
        wx.z = hx1[2] - CFLF * s3b[2];
        wx.w = hx1[3] - CFLF * s3b[3];
        *reinterpret_cast<float4*>(out_base + hxo_off + b * HXN + (i0 + 1) * HXW + j) = wx;

        // Hy stores: odd stride, scalar
        float* hyw0 = out_base + hyo_off + b * HYN + i0 * HYW + j;
        float* hyw1 = hyw0 + HYW;
        #pragma unroll
        for (int q = 0; q < 4; q++) {
            hyw0[q] = hy0[q] + CFLF * s4a[q];
            hyw1[q] = hy1[q] + CFLF * s4b[q];
        }
    } else {
        const float* Eb  = e_base + eb;
        const float* Hxb = hx_base + xb;
        const float* Hyb = hy_base + yb;
        float* Hxob = out_base + hxo_off + b * HXN;
        float* Hyob = out_base + hyo_off + b * HYN;
        #pragma unroll
        for (int r = 0; r < 2; r++) {
            int ii = i0 + r;
            if (ii >= NN) continue;
            #pragma unroll
            for (int q = 0; q < 4; q++) {
                int jj = j + q;
                if (jj < 0 || jj >= NN) continue;
                if (ii < HXH && jj < HXW) {
                    float s3 = faraday_s3(Eb, ii, jj, m);
                    Hxob[ii * HXW + jj] = Hxb[ii * HXW + jj] - CFLF * s3;
                }
                if (ii < HYH && jj < HYW) {
                    float s4 = faraday_s4(Eb, ii, jj, m);
                    Hyob[ii * HYW + jj] = Hyb[ii * HYW + jj] + CFLF * s4;
                }
            }
        }
    }
}

// ---------------------------------------------------------------------------
extern "C" void kernel_launch(void* const* d_in, const int* in_sizes, int n_in,
                              void* d_out, int out_size)
{
    const float* sb = (const float*)d_in[3];
    const float* sd = (const float*)d_in[4];
    const float* sg = (const float*)d_in[5];
    float* out = (float*)d_out;

    const float* e_base  = (const float*)d_in[0]; int e_off  = 0;
    const float* hx_base = (const float*)d_in[1]; int hx_off = 0;
    const float* hy_base = (const float*)d_in[2]; int hy_off = 0;

    const int STEP = BB * (EN + HXN + HYN);

    dim3 blk(32, 4, 1);
    dim3 gE(17, (1025 + 3) / 4, BB);   // 1025 row-pairs cover 2049 rows
    dim3 gF(17, 1024 / 4, BB);         // 1024 row-pairs cover 2048 rows

    for (int k = 0; k < 3; k++) {
        int eo_off  = k * STEP;
        int hxo_off = eo_off + BB * EN;
        int hyo_off = hxo_off + BB * HXN;

        k_amper<<<gE, blk>>>(e_base, e_off, hx_base, hx_off, hy_base, hy_off,
                             out, eo_off, sb, sd, sg);
        k_faraday<<<gF, blk>>>(out, eo_off, hx_base, hx_off, hy_base, hy_off,
                               out, hxo_off, hyo_off, sb, sd, sg);

        e_base = out;  e_off  = eo_off;
        hx_base = out; hx_off = hxo_off;
        hy_base = out; hy_off = hyo_off;
    }
}